// round 2
// baseline (speedup 1.0000x reference)
#include <cuda_runtime.h>
#include <cuda_bf16.h>

// ---------------------------------------------------------------------------
// 9-wire statevector simulator. One warp per batch item, 16 complex amps/lane.
// Amplitude index idx[8:0]: wire w <-> bit (8-w).
//   wires 0..4  -> lane bits 4..0   (communication via __shfl_xor_sync)
//   wires 5..8  -> reg  bits 3..0   (pure register ops)
// ---------------------------------------------------------------------------

#define N_COEF 792   // 72 entangle steps * 8 floats + 27 Rot gates * 8 floats
__device__ float g_coef[N_COEF];

template<int V> struct IC { static constexpr int value = V; };

template<int N, typename F>
__device__ __forceinline__ void static_for(F&& f) {
    if constexpr (N > 0) {
        static_for<N - 1>(f);
        f(IC<N - 1>{});
    }
}

__device__ __forceinline__ float2 shflx(float2 v, int m) {
    float2 r;
    r.x = __shfl_xor_sync(0xffffffffu, v.x, m);
    r.y = __shfl_xor_sync(0xffffffffu, v.y, m);
    return r;
}

// ------------------------------ gates --------------------------------------

// RX(t): [[c, -i s], [-i s, c]]   (self-symmetric: out = c*self + (-i s)*other)
template<int W>
__device__ __forceinline__ void g_rx(float2 (&s)[16], float c, float sn, int lane) {
    if constexpr (W >= 5) {
        constexpr int M = 1 << (8 - W);
#pragma unroll
        for (int r = 0; r < 16; r++) if (!(r & M)) {
            float2 a = s[r], b = s[r | M];
            s[r]     = make_float2(c * a.x + sn * b.y, c * a.y - sn * b.x);
            s[r | M] = make_float2(c * b.x + sn * a.y, c * b.y - sn * a.x);
        }
    } else {
        constexpr int LM = 1 << (4 - W);
#pragma unroll
        for (int r = 0; r < 16; r++) {
            float2 p = shflx(s[r], LM);
            float2 a = s[r];
            s[r] = make_float2(c * a.x + sn * p.y, c * a.y - sn * p.x);
        }
    }
}

// RY(t): [[c, -s], [s, c]] (real)
template<int W>
__device__ __forceinline__ void g_ry(float2 (&s)[16], float c, float sn, int lane) {
    if constexpr (W >= 5) {
        constexpr int M = 1 << (8 - W);
#pragma unroll
        for (int r = 0; r < 16; r++) if (!(r & M)) {
            float2 a = s[r], b = s[r | M];
            s[r]     = make_float2(c * a.x - sn * b.x, c * a.y - sn * b.y);
            s[r | M] = make_float2(sn * a.x + c * b.x, sn * a.y + c * b.y);
        }
    } else {
        constexpr int LM = 1 << (4 - W);
        float Bs = (lane & LM) ? sn : -sn;
#pragma unroll
        for (int r = 0; r < 16; r++) {
            float2 p = shflx(s[r], LM);
            float2 a = s[r];
            s[r] = make_float2(c * a.x + Bs * p.x, c * a.y + Bs * p.y);
        }
    }
}

// Pauli-X on wire W
template<int W>
__device__ __forceinline__ void g_x(float2 (&s)[16], int lane) {
    if constexpr (W >= 5) {
        constexpr int M = 1 << (8 - W);
#pragma unroll
        for (int r = 0; r < 16; r++) if (!(r & M)) {
            float2 t = s[r]; s[r] = s[r | M]; s[r | M] = t;
        }
    } else {
        constexpr int LM = 1 << (4 - W);
#pragma unroll
        for (int r = 0; r < 16; r++) s[r] = shflx(s[r], LM);
    }
}

// CNOT control C target T
template<int C, int T>
__device__ __forceinline__ void g_cnot(float2 (&s)[16], int lane) {
    if constexpr (C >= 5 && T >= 5) {
        constexpr int MC = 1 << (8 - C), MT = 1 << (8 - T);
#pragma unroll
        for (int r = 0; r < 16; r++) if ((r & MC) && !(r & MT)) {
            float2 t = s[r]; s[r] = s[r | MT]; s[r | MT] = t;
        }
    } else if constexpr (C >= 5 && T < 5) {
        constexpr int MC = 1 << (8 - C), LMT = 1 << (4 - T);
#pragma unroll
        for (int r = 0; r < 16; r++) if (r & MC) {
            s[r] = shflx(s[r], LMT);
        }
    } else if constexpr (C < 5 && T >= 5) {
        constexpr int LMC = 1 << (4 - C), MT = 1 << (8 - T);
        bool cb = (lane & LMC) != 0;
#pragma unroll
        for (int r = 0; r < 16; r++) if (!(r & MT)) {
            float2 a = s[r], b = s[r | MT];
            s[r]      = cb ? b : a;
            s[r | MT] = cb ? a : b;
        }
    } else {
        constexpr int LMC = 1 << (4 - C), LMT = 1 << (4 - T);
        bool cb = (lane & LMC) != 0;
#pragma unroll
        for (int r = 0; r < 16; r++) {
            float2 p = shflx(s[r], LMT);
            if (cb) s[r] = p;
        }
    }
}

// CRZ(t) control C target T: on c=1 multiply by (cz, tbit ? +sz : -sz). Diagonal.
template<int C, int T>
__device__ __forceinline__ void g_crz(float2 (&s)[16], float c, float sn, int lane) {
    if constexpr (C >= 5) {
        constexpr int MC = 1 << (8 - C);
        float ps_lane = 0.f;
        if constexpr (T < 5) ps_lane = (lane & (1 << (4 - T))) ? sn : -sn;
#pragma unroll
        for (int r = 0; r < 16; r++) if (r & MC) {
            float ps;
            if constexpr (T >= 5) ps = (r & (1 << (8 - T))) ? sn : -sn;
            else ps = ps_lane;
            float2 a = s[r];
            s[r] = make_float2(a.x * c - a.y * ps, a.x * ps + a.y * c);
        }
    } else {
        constexpr int LMC = 1 << (4 - C);
        bool cb = (lane & LMC) != 0;
        float ps_lane = 0.f;
        if constexpr (T < 5) ps_lane = (lane & (1 << (4 - T))) ? sn : -sn;
#pragma unroll
        for (int r = 0; r < 16; r++) {
            float ps;
            if constexpr (T >= 5) ps = (r & (1 << (8 - T))) ? sn : -sn;
            else ps = ps_lane;
            float2 a = s[r];
            float2 nv = make_float2(a.x * c - a.y * ps, a.x * ps + a.y * c);
            if (cb) s[r] = nv;
        }
    }
}

// CRX(t) control C target T: on c=1 apply RX(t) to T.
template<int C, int T>
__device__ __forceinline__ void g_crx(float2 (&s)[16], float c, float sn, int lane) {
    if constexpr (T >= 5) {
        constexpr int MT = 1 << (8 - T);
        if constexpr (C >= 5) {
            constexpr int MC = 1 << (8 - C);
#pragma unroll
            for (int r = 0; r < 16; r++) if ((r & MC) && !(r & MT)) {
                float2 a = s[r], b = s[r | MT];
                s[r]      = make_float2(c * a.x + sn * b.y, c * a.y - sn * b.x);
                s[r | MT] = make_float2(c * b.x + sn * a.y, c * b.y - sn * a.x);
            }
        } else {
            bool cb = (lane & (1 << (4 - C))) != 0;
#pragma unroll
            for (int r = 0; r < 16; r++) if (!(r & MT)) {
                float2 a = s[r], b = s[r | MT];
                float2 na = make_float2(c * a.x + sn * b.y, c * a.y - sn * b.x);
                float2 nb = make_float2(c * b.x + sn * a.y, c * b.y - sn * a.x);
                if (cb) { s[r] = na; s[r | MT] = nb; }
            }
        }
    } else {
        constexpr int LMT = 1 << (4 - T);
        if constexpr (C >= 5) {
            constexpr int MC = 1 << (8 - C);
#pragma unroll
            for (int r = 0; r < 16; r++) if (r & MC) {
                float2 p = shflx(s[r], LMT);
                float2 a = s[r];
                s[r] = make_float2(c * a.x + sn * p.y, c * a.y - sn * p.x);
            }
        } else {
            bool cb = (lane & (1 << (4 - C))) != 0;
#pragma unroll
            for (int r = 0; r < 16; r++) {
                float2 p = shflx(s[r], LMT);
                float2 a = s[r];
                float2 nv = make_float2(c * a.x + sn * p.y, c * a.y - sn * p.x);
                if (cb) s[r] = nv;
            }
        }
    }
}

// Generic complex 2x2 (Rot gate)
template<int W>
__device__ __forceinline__ void g_1q(float2 (&s)[16], float2 u00, float2 u01,
                                     float2 u10, float2 u11, int lane) {
    if constexpr (W >= 5) {
        constexpr int M = 1 << (8 - W);
#pragma unroll
        for (int r = 0; r < 16; r++) if (!(r & M)) {
            float2 a = s[r], b = s[r | M];
            s[r] = make_float2(
                u00.x * a.x - u00.y * a.y + u01.x * b.x - u01.y * b.y,
                u00.x * a.y + u00.y * a.x + u01.x * b.y + u01.y * b.x);
            s[r | M] = make_float2(
                u10.x * a.x - u10.y * a.y + u11.x * b.x - u11.y * b.y,
                u10.x * a.y + u10.y * a.x + u11.x * b.y + u11.y * b.x);
        }
    } else {
        constexpr int LM = 1 << (4 - W);
        bool bit = (lane & LM) != 0;
        float2 A  = bit ? u11 : u00;
        float2 Bc = bit ? u10 : u01;
#pragma unroll
        for (int r = 0; r < 16; r++) {
            float2 p = shflx(s[r], LM);
            float2 a = s[r];
            s[r] = make_float2(
                A.x * a.x - A.y * a.y + Bc.x * p.x - Bc.y * p.y,
                A.x * a.y + A.y * a.x + Bc.x * p.y + Bc.y * p.x);
        }
    }
}

// One entangle step i: RY(i), RY(ip), CNOT, CRZ, X(ip), CRX   with ip=(i+1)%9
__device__ __forceinline__ void ent_block(float2 (&s)[16], const float* cf, int lane) {
    static_for<9>([&](auto ic) {
        constexpr int I  = decltype(ic)::value;
        constexpr int IP = (I + 1) % 9;
        const float* c = cf + I * 8;
        float ryc0 = c[0], rys0 = c[1];
        float ryc1 = c[2], rys1 = c[3];
        float czc  = c[4], czs  = c[5];
        float cxc  = c[6], cxs  = c[7];
        g_ry<I>(s, ryc0, rys0, lane);
        g_ry<IP>(s, ryc1, rys1, lane);
        g_cnot<I, IP>(s, lane);
        g_crz<I, IP>(s, czc, czs, lane);
        g_x<IP>(s, lane);
        g_crx<I, IP>(s, cxc, cxs, lane);
    });
}

// ------------------------- coefficient prep kernel -------------------------
// entangle coef: slot t in [0,72): block b=t/9, step i=t%9 -> 8 floats
// Rot coef:      slot t-72 in [0,27): layer l, wire i       -> 8 floats (u matrix)
__global__ void prep_kernel(const float* __restrict__ params,
                            const float* __restrict__ weights,
                            const float* __restrict__ params2) {
    int t = threadIdx.x;
    if (t < 72) {
        int b = t / 9, i = t % 9;
        const float* p = (b < 3) ? (params + b * 36 + i * 4)
                                 : (params2 + (b - 3) * 36 + i * 4);
        float* o = g_coef + t * 8;
        float c, s;
        sincosf(0.5f * p[0], &s, &c); o[0] = c; o[1] = s;   // RY(i)
        sincosf(0.5f * p[1], &s, &c); o[2] = c; o[3] = s;   // RY(ip)
        sincosf(0.5f * p[2], &s, &c); o[4] = c; o[5] = s;   // CRZ
        sincosf(0.5f * p[3], &s, &c); o[6] = c; o[7] = s;   // CRX
    } else if (t < 99) {
        int idx = t - 72;
        int l = idx / 9, i = idx % 9;
        const float* w = weights + (l * 9 + i) * 3;
        float phi = w[0], th = w[1], om = w[2];
        float ct, st; sincosf(0.5f * th, &st, &ct);
        float aa = 0.5f * (phi + om), bb = 0.5f * (phi - om);
        float ca, sa; sincosf(aa, &sa, &ca);
        float cb, sb; sincosf(bb, &sb, &cb);
        float* o = g_coef + 576 + idx * 8;
        // Rot = RZ(om) RY(th) RZ(phi)
        o[0] =  ct * ca; o[1] = -ct * sa;   // u00 = ct e^{-i(phi+om)/2}
        o[2] = -st * cb; o[3] = -st * sb;   // u01 = -st e^{+i(phi-om)/2}
        o[4] =  st * cb; o[5] = -st * sb;   // u10 =  st e^{-i(phi-om)/2}
        o[6] =  ct * ca; o[7] =  ct * sa;   // u11 = ct e^{+i(phi+om)/2}
    }
}

// ------------------------------- sim kernel --------------------------------
__global__ void __launch_bounds__(128, 4)
sim_kernel(const float* __restrict__ adds, float* __restrict__ out, int B) {
    __shared__ float sh[N_COEF];
    for (int i = threadIdx.x; i < N_COEF; i += blockDim.x) sh[i] = g_coef[i];
    __syncthreads();

    int lane = threadIdx.x & 31;
    int item = blockIdx.x * (blockDim.x >> 5) + (threadIdx.x >> 5);
    if (item >= B) return;

    // per-sample embedding angles: lane w (<9) computes sincos for wire w
    float ec = 1.f, es = 0.f;
    if (lane < 9) {
        float a = adds[item * 9 + lane];
        sincosf(0.5f * a, &es, &ec);
    }

    float2 s[16];
#pragma unroll
    for (int r = 0; r < 16; r++) s[r] = make_float2(0.f, 0.f);
    if (lane == 0) s[0] = make_float2(1.f, 0.f);

    // AngleEmbedding: RX(adds[:, w]) on wire w
    static_for<9>([&](auto ic) {
        constexpr int W = decltype(ic)::value;
        float c  = __shfl_sync(0xffffffffu, ec, W);
        float sn = __shfl_sync(0xffffffffu, es, W);
        g_rx<W>(s, c, sn, lane);
    });

    // 3 QRAM entangle blocks
    for (int b = 0; b < 3; b++) ent_block(s, sh + b * 72, lane);

    // 3 StronglyEntanglingLayers (range r = L+1)
    static_for<3>([&](auto lc) {
        constexpr int L = decltype(lc)::value;
        static_for<9>([&](auto ic) {
            constexpr int I = decltype(ic)::value;
            const float* o = sh + 576 + (L * 9 + I) * 8;
            g_1q<I>(s, make_float2(o[0], o[1]), make_float2(o[2], o[3]),
                       make_float2(o[4], o[5]), make_float2(o[6], o[7]), lane);
        });
        static_for<9>([&](auto ic) {
            constexpr int I = decltype(ic)::value;
            g_cnot<I, (I + L + 1) % 9>(s, lane);
        });
    });

    // 5 classifier entangle blocks
    for (int b = 3; b < 8; b++) ent_block(s, sh + b * 72, lane);

    // <Z0>: wire 0 = lane bit 4
    float acc = 0.f;
#pragma unroll
    for (int r = 0; r < 16; r++) acc += s[r].x * s[r].x + s[r].y * s[r].y;
    if (lane & 16) acc = -acc;
#pragma unroll
    for (int m = 16; m >= 1; m >>= 1) acc += __shfl_xor_sync(0xffffffffu, acc, m);
    if (lane == 0) out[item] = acc;
}

// ------------------------------ launcher -----------------------------------
extern "C" void kernel_launch(void* const* d_in, const int* in_sizes, int n_in,
                              void* d_out, int out_size) {
    const float* adds    = (const float*)d_in[0];
    const float* params  = (const float*)d_in[1];
    const float* weights = (const float*)d_in[2];
    const float* params2 = (const float*)d_in[3];
    float* out = (float*)d_out;

    int B = in_sizes[0] / 9;

    prep_kernel<<<1, 128>>>(params, weights, params2);

    int warpsPerBlock = 4;
    int blocks = (B + warpsPerBlock - 1) / warpsPerBlock;
    sim_kernel<<<blocks, 128>>>(adds, out, B);
}

// round 4
// speedup vs baseline: 1.4683x; 1.4683x over previous
#include <cuda_runtime.h>
#include <cuda_bf16.h>

// ---------------------------------------------------------------------------
// 9-wire statevector simulator. One warp per batch item, 16 complex amps/lane,
// amplitudes stored PACKED (re,im) in 64-bit regs, gate math via f32x2 FMA.
// Amplitude index idx[8:0]: wire w <-> bit (8-w).
//   wires 0..4  -> lane bits 4..0   (communication via shuffles)
//   wires 5..8  -> reg  bits 3..0   (pure register ops)
// ---------------------------------------------------------------------------

using u64 = unsigned long long;

#define N_COEF 792   // 72 entangle steps * 8 floats + 27 Rot gates * 8 floats
__device__ float g_coef[N_COEF];

template<int V> struct IC { static constexpr int value = V; };
template<int N, typename F>
__device__ __forceinline__ void static_for(F&& f) {
    if constexpr (N > 0) { static_for<N - 1>(f); f(IC<N - 1>{}); }
}

// ------------------------- packed f32x2 helpers ----------------------------
__device__ __forceinline__ u64 pk2(float lo, float hi) {
    u64 r;
    asm("mov.b64 %0, {%1, %2};" : "=l"(r)
        : "r"(__float_as_uint(lo)), "r"(__float_as_uint(hi)));
    return r;
}
__device__ __forceinline__ void upk2(u64 a, float& lo, float& hi) {
    unsigned l_, h_;
    asm("mov.b64 {%0, %1}, %2;" : "=r"(l_), "=r"(h_) : "l"(a));
    lo = __uint_as_float(l_); hi = __uint_as_float(h_);
}
__device__ __forceinline__ u64 bcast(float x) { return pk2(x, x); }
__device__ __forceinline__ u64 swp(u64 a) {
    float x, y; upk2(a, x, y); return pk2(y, x);
}
__device__ __forceinline__ u64 ffma2(u64 a, u64 b, u64 c) {
    u64 d; asm("fma.rn.f32x2 %0, %1, %2, %3;" : "=l"(d) : "l"(a), "l"(b), "l"(c));
    return d;
}
__device__ __forceinline__ u64 fmul2(u64 a, u64 b) {
    u64 d; asm("mul.rn.f32x2 %0, %1, %2;" : "=l"(d) : "l"(a), "l"(b));
    return d;
}
__device__ __forceinline__ u64 shx(u64 v, int m)   { return __shfl_xor_sync(0xffffffffu, v, m); }
__device__ __forceinline__ u64 shi(u64 v, int src) { return __shfl_sync(0xffffffffu, v, src); }

// ------------------------------ gates --------------------------------------
// Complex value z packed as (re, im). For scalar u (complex):
//   u*z = bcast(ur)*z + pk2(-ui, ui)*swp(z)

// RX(t): out = c*a + (sn, -sn) .* swp(partner)
template<int W>
__device__ __forceinline__ void g_rx(u64 (&s)[16], float c, float sn, int lane) {
    u64 C = bcast(c), S = pk2(sn, -sn);
    if constexpr (W >= 5) {
        constexpr int M = 1 << (8 - W);
#pragma unroll
        for (int r = 0; r < 16; r++) if (!(r & M)) {
            u64 a = s[r], b = s[r | M];
            s[r]     = ffma2(S, swp(b), fmul2(C, a));
            s[r | M] = ffma2(S, swp(a), fmul2(C, b));
        }
    } else {
        constexpr int LM = 1 << (4 - W);
#pragma unroll
        for (int r = 0; r < 16; r++) {
            u64 p = shx(s[r], LM);
            s[r] = ffma2(S, swp(p), fmul2(C, s[r]));
        }
    }
}

// RY(t): real rotation, componentwise
template<int W>
__device__ __forceinline__ void g_ry(u64 (&s)[16], float c, float sn, int lane) {
    if constexpr (W >= 5) {
        constexpr int M = 1 << (8 - W);
        u64 Cc = bcast(c), Sp = bcast(sn), Sm = bcast(-sn);
#pragma unroll
        for (int r = 0; r < 16; r++) if (!(r & M)) {
            u64 a = s[r], b = s[r | M];
            s[r]     = ffma2(Sm, b, fmul2(Cc, a));
            s[r | M] = ffma2(Sp, a, fmul2(Cc, b));
        }
    } else {
        constexpr int LM = 1 << (4 - W);
        u64 Cc = bcast(c), Bs = bcast((lane & LM) ? sn : -sn);
#pragma unroll
        for (int r = 0; r < 16; r++) {
            u64 p = shx(s[r], LM);
            s[r] = ffma2(Bs, p, fmul2(Cc, s[r]));
        }
    }
}

// CNOT control C target T
template<int C, int T>
__device__ __forceinline__ void g_cnot(u64 (&s)[16], int lane) {
    if constexpr (C >= 5 && T >= 5) {
        constexpr int MC = 1 << (8 - C), MT = 1 << (8 - T);
#pragma unroll
        for (int r = 0; r < 16; r++) if ((r & MC) && !(r & MT)) {
            u64 t = s[r]; s[r] = s[r | MT]; s[r | MT] = t;
        }
    } else if constexpr (C >= 5) {           // T low
        constexpr int MC = 1 << (8 - C), LMT = 1 << (4 - T);
#pragma unroll
        for (int r = 0; r < 16; r++) if (r & MC) s[r] = shx(s[r], LMT);
    } else if constexpr (T >= 5) {           // C low
        constexpr int LMC = 1 << (4 - C), MT = 1 << (8 - T);
        bool cb = (lane & LMC) != 0;
#pragma unroll
        for (int r = 0; r < 16; r++) if (!(r & MT)) {
            u64 a = s[r], b = s[r | MT];
            s[r]      = cb ? b : a;
            s[r | MT] = cb ? a : b;
        }
    } else {                                  // both low: single variable shuffle
        constexpr int LMC = 1 << (4 - C), LMT = 1 << (4 - T);
        int src = lane ^ ((lane & LMC) ? LMT : 0);
#pragma unroll
        for (int r = 0; r < 16; r++) s[r] = shi(s[r], src);
    }
}

// CRZ(t): diagonal phase on control=1; ps sign follows target bit.
// out = (c)*a + (-ps, ps) .* swp(a)
template<int C, int T>
__device__ __forceinline__ void g_crz(u64 (&s)[16], float c, float sn, int lane) {
    if constexpr (C >= 5) {
        constexpr int MC = 1 << (8 - C);
        u64 Cc = bcast(c);
        if constexpr (T >= 5) {
            constexpr int MT = 1 << (8 - T);
            u64 Pp = pk2(-sn, sn), Pm = pk2(sn, -sn);
#pragma unroll
            for (int r = 0; r < 16; r++) if (r & MC) {
                u64 P = (r & MT) ? Pp : Pm;
                s[r] = ffma2(P, swp(s[r]), fmul2(Cc, s[r]));
            }
        } else {
            constexpr int LMT = 1 << (4 - T);
            float ps = (lane & LMT) ? sn : -sn;
            u64 P = pk2(-ps, ps);
#pragma unroll
            for (int r = 0; r < 16; r++) if (r & MC)
                s[r] = ffma2(P, swp(s[r]), fmul2(Cc, s[r]));
        }
    } else {
        constexpr int LMC = 1 << (4 - C);
        bool cb = (lane & LMC) != 0;
        u64 Cc = bcast(cb ? c : 1.f);
        if constexpr (T >= 5) {
            constexpr int MT = 1 << (8 - T);
            float se = cb ? sn : 0.f;
            u64 Pp = pk2(-se, se), Pm = pk2(se, -se);
#pragma unroll
            for (int r = 0; r < 16; r++) {
                u64 P = (r & MT) ? Pp : Pm;
                s[r] = ffma2(P, swp(s[r]), fmul2(Cc, s[r]));
            }
        } else {
            constexpr int LMT = 1 << (4 - T);
            float pse = cb ? ((lane & LMT) ? sn : -sn) : 0.f;
            u64 P = pk2(-pse, pse);
#pragma unroll
            for (int r = 0; r < 16; r++)
                s[r] = ffma2(P, swp(s[r]), fmul2(Cc, s[r]));
        }
    }
}

// Fused X(T) then CRX(C,T).
// With control satisfied: new(self) = c*partner + (sn,-sn).*swp(self)
// With control clear (or eff-coef 1/0): new = partner (pure X).
template<int C, int T>
__device__ __forceinline__ void g_xcrx(u64 (&s)[16], float c, float sn, int lane) {
    if constexpr (T >= 5) {
        constexpr int MT = 1 << (8 - T);
        if constexpr (C >= 5) {
            constexpr int MC = 1 << (8 - C);
            u64 Cc = bcast(c), S = pk2(sn, -sn);
#pragma unroll
            for (int r = 0; r < 16; r++) if (!(r & MT)) {
                u64 a = s[r], b = s[r | MT];
                if (r & MC) {
                    s[r]      = ffma2(S, swp(a), fmul2(Cc, b));
                    s[r | MT] = ffma2(S, swp(b), fmul2(Cc, a));
                } else { s[r] = b; s[r | MT] = a; }
            }
        } else {
            constexpr int LMC = 1 << (4 - C);
            bool cb = (lane & LMC) != 0;
            u64 Cc = bcast(cb ? c : 1.f);
            float se = cb ? sn : 0.f;
            u64 S = pk2(se, -se);
#pragma unroll
            for (int r = 0; r < 16; r++) if (!(r & MT)) {
                u64 a = s[r], b = s[r | MT];
                s[r]      = ffma2(S, swp(a), fmul2(Cc, b));
                s[r | MT] = ffma2(S, swp(b), fmul2(Cc, a));
            }
        }
    } else {
        constexpr int LMT = 1 << (4 - T);
        if constexpr (C >= 5) {
            constexpr int MC = 1 << (8 - C);
            u64 Cc = bcast(c), S = pk2(sn, -sn);
#pragma unroll
            for (int r = 0; r < 16; r++) {
                u64 p = shx(s[r], LMT);               // X-applied value
                if (r & MC) s[r] = ffma2(S, swp(s[r]), fmul2(Cc, p));
                else        s[r] = p;
            }
        } else {
            constexpr int LMC = 1 << (4 - C);
            bool cb = (lane & LMC) != 0;
            u64 Cc = bcast(cb ? c : 1.f);
            float se = cb ? sn : 0.f;
            u64 S = pk2(se, -se);
#pragma unroll
            for (int r = 0; r < 16; r++) {
                u64 p = shx(s[r], LMT);
                s[r] = ffma2(S, swp(s[r]), fmul2(Cc, p));
            }
        }
    }
}

// Generic complex 2x2 (Rot). o: u00r,u00i,u01r,u01i,u10r,u10i,u11r,u11i
template<int W>
__device__ __forceinline__ void g_rot(u64 (&s)[16], const float* o, int lane) {
    if constexpr (W >= 5) {
        constexpr int M = 1 << (8 - W);
        u64 U00r = bcast(o[0]), U00i = pk2(-o[1], o[1]);
        u64 U01r = bcast(o[2]), U01i = pk2(-o[3], o[3]);
        u64 U10r = bcast(o[4]), U10i = pk2(-o[5], o[5]);
        u64 U11r = bcast(o[6]), U11i = pk2(-o[7], o[7]);
#pragma unroll
        for (int r = 0; r < 16; r++) if (!(r & M)) {
            u64 a = s[r], b = s[r | M], sa = swp(a), sb = swp(b);
            u64 na = ffma2(U01i, sb, ffma2(U01r, b, ffma2(U00i, sa, fmul2(U00r, a))));
            u64 nb = ffma2(U11i, sb, ffma2(U11r, b, ffma2(U10i, sa, fmul2(U10r, a))));
            s[r] = na; s[r | M] = nb;
        }
    } else {
        constexpr int LM = 1 << (4 - W);
        bool bit = (lane & LM) != 0;
        float Ar = bit ? o[6] : o[0], Ai = bit ? o[7] : o[1];
        float Br = bit ? o[4] : o[2], Bi = bit ? o[5] : o[3];
        u64 ARe = bcast(Ar), AIm = pk2(-Ai, Ai);
        u64 BRe = bcast(Br), BIm = pk2(-Bi, Bi);
#pragma unroll
        for (int r = 0; r < 16; r++) {
            u64 p = shx(s[r], LM), a = s[r];
            s[r] = ffma2(BIm, swp(p), ffma2(BRe, p, ffma2(AIm, swp(a), fmul2(ARe, a))));
        }
    }
}

// One entangle step i: RY(i), RY(ip), CNOT, CRZ, fused X+CRX   ip=(i+1)%9
__device__ __forceinline__ void ent_block(u64 (&s)[16], const float* cf, int lane) {
    static_for<9>([&](auto ic) {
        constexpr int I  = decltype(ic)::value;
        constexpr int IP = (I + 1) % 9;
        const float* c = cf + I * 8;
        float ryc0 = c[0], rys0 = c[1];
        float ryc1 = c[2], rys1 = c[3];
        float czc  = c[4], czs  = c[5];
        float cxc  = c[6], cxs  = c[7];
        g_ry<I>(s, ryc0, rys0, lane);
        g_ry<IP>(s, ryc1, rys1, lane);
        g_cnot<I, IP>(s, lane);
        g_crz<I, IP>(s, czc, czs, lane);
        g_xcrx<I, IP>(s, cxc, cxs, lane);
    });
}

// ------------------------- coefficient prep kernel -------------------------
__global__ void prep_kernel(const float* __restrict__ params,
                            const float* __restrict__ weights,
                            const float* __restrict__ params2) {
    int t = threadIdx.x;
    if (t < 72) {
        int b = t / 9, i = t % 9;
        const float* p = (b < 3) ? (params + b * 36 + i * 4)
                                 : (params2 + (b - 3) * 36 + i * 4);
        float* o = g_coef + t * 8;
        float c, s;
        sincosf(0.5f * p[0], &s, &c); o[0] = c; o[1] = s;   // RY(i)
        sincosf(0.5f * p[1], &s, &c); o[2] = c; o[3] = s;   // RY(ip)
        sincosf(0.5f * p[2], &s, &c); o[4] = c; o[5] = s;   // CRZ
        sincosf(0.5f * p[3], &s, &c); o[6] = c; o[7] = s;   // CRX
    } else if (t < 99) {
        int idx = t - 72;
        int l = idx / 9, i = idx % 9;
        const float* w = weights + (l * 9 + i) * 3;
        float phi = w[0], th = w[1], om = w[2];
        float ct, st; sincosf(0.5f * th, &st, &ct);
        float aa = 0.5f * (phi + om), bb = 0.5f * (phi - om);
        float ca, sa; sincosf(aa, &sa, &ca);
        float cb, sb; sincosf(bb, &sb, &cb);
        float* o = g_coef + 576 + idx * 8;
        o[0] =  ct * ca; o[1] = -ct * sa;   // u00
        o[2] = -st * cb; o[3] = -st * sb;   // u01
        o[4] =  st * cb; o[5] = -st * sb;   // u10
        o[6] =  ct * ca; o[7] =  ct * sa;   // u11
    }
}

// ------------------------------- sim kernel --------------------------------
__global__ void __launch_bounds__(128, 5)
sim_kernel(const float* __restrict__ adds, float* __restrict__ out, int B) {
    __shared__ float sh[N_COEF];
    for (int i = threadIdx.x; i < N_COEF; i += blockDim.x) sh[i] = g_coef[i];
    __syncthreads();

    int lane = threadIdx.x & 31;
    int item = blockIdx.x * (blockDim.x >> 5) + (threadIdx.x >> 5);
    if (item >= B) return;

    // per-sample embedding angles: lane w (<9) computes sincos for wire w
    float ec = 1.f, es = 0.f;
    if (lane < 9) {
        float a = adds[item * 9 + lane];
        sincosf(0.5f * a, &es, &ec);
    }

    u64 s[16];
#pragma unroll
    for (int r = 0; r < 16; r++) s[r] = 0ull;
    if (lane == 0) s[0] = pk2(1.f, 0.f);

    // AngleEmbedding: RX(adds[:, w]) on wire w
    static_for<9>([&](auto ic) {
        constexpr int W = decltype(ic)::value;
        float c  = __shfl_sync(0xffffffffu, ec, W);
        float sn = __shfl_sync(0xffffffffu, es, W);
        g_rx<W>(s, c, sn, lane);
    });

    // 3 QRAM entangle blocks
    for (int b = 0; b < 3; b++) ent_block(s, sh + b * 72, lane);

    // 3 StronglyEntanglingLayers (range r = L+1)
    static_for<3>([&](auto lc) {
        constexpr int L = decltype(lc)::value;
        static_for<9>([&](auto ic) {
            constexpr int I = decltype(ic)::value;
            g_rot<I>(s, sh + 576 + (L * 9 + I) * 8, lane);
        });
        static_for<9>([&](auto ic) {
            constexpr int I = decltype(ic)::value;
            g_cnot<I, (I + L + 1) % 9>(s, lane);
        });
    });

    // 5 classifier entangle blocks
    for (int b = 3; b < 8; b++) ent_block(s, sh + b * 72, lane);

    // <Z0>: wire 0 = lane bit 4
    float acc = 0.f;
#pragma unroll
    for (int r = 0; r < 16; r++) {
        float x, y; upk2(s[r], x, y);
        acc += x * x + y * y;
    }
    if (lane & 16) acc = -acc;
#pragma unroll
    for (int m = 16; m >= 1; m >>= 1) acc += __shfl_xor_sync(0xffffffffu, acc, m);
    if (lane == 0) out[item] = acc;
}

// ------------------------------ launcher -----------------------------------
extern "C" void kernel_launch(void* const* d_in, const int* in_sizes, int n_in,
                              void* d_out, int out_size) {
    const float* adds    = (const float*)d_in[0];
    const float* params  = (const float*)d_in[1];
    const float* weights = (const float*)d_in[2];
    const float* params2 = (const float*)d_in[3];
    float* out = (float*)d_out;

    int B = in_sizes[0] / 9;

    prep_kernel<<<1, 128>>>(params, weights, params2);

    int warpsPerBlock = 4;
    int blocks = (B + warpsPerBlock - 1) / warpsPerBlock;
    sim_kernel<<<blocks, 128>>>(adds, out, B);
}

// round 6
// speedup vs baseline: 1.8762x; 1.2778x over previous
#include <cuda_runtime.h>
#include <cuda_bf16.h>

// ---------------------------------------------------------------------------
// 9-wire statevector simulator. One warp per batch item, 16 complex amps/lane,
// amplitudes stored PACKED (re,im) in 64-bit regs, gate math via f32x2 FMA.
// Amplitude index idx[8:0]: wire w <-> bit (8-w).
//   wires 0..4  -> lane bits 4..0   (communication via shuffles)
//   wires 5..8  -> reg  bits 3..0   (pure register ops)
//
// R4: per entangle step, RY(ip)*CNOT*CRZ*X*CRX fused into one controlled-2x2
//     gate W (block-diagonal in control). Embedding replaced by direct
//     tensor-product initialization.
// ---------------------------------------------------------------------------

using u64 = unsigned long long;

#define ENT_STRIDE 12            // per-step coef floats: ca,sa, sb,cb, W1[8]
#define ROT_OFF    (72 * ENT_STRIDE)
#define N_COEF     (ROT_OFF + 27 * 8)
__device__ float g_coef[N_COEF];

template<int V> struct IC { static constexpr int value = V; };
template<int N, typename F>
__device__ __forceinline__ void static_for(F&& f) {
    if constexpr (N > 0) { static_for<N - 1>(f); f(IC<N - 1>{}); }
}

// ------------------------- packed f32x2 helpers ----------------------------
__device__ __forceinline__ u64 pk2(float lo, float hi) {
    u64 r;
    asm("mov.b64 %0, {%1, %2};" : "=l"(r)
        : "r"(__float_as_uint(lo)), "r"(__float_as_uint(hi)));
    return r;
}
__device__ __forceinline__ void upk2(u64 a, float& lo, float& hi) {
    unsigned l_, h_;
    asm("mov.b64 {%0, %1}, %2;" : "=r"(l_), "=r"(h_) : "l"(a));
    lo = __uint_as_float(l_); hi = __uint_as_float(h_);
}
__device__ __forceinline__ u64 bcast(float x) { return pk2(x, x); }
__device__ __forceinline__ u64 swp(u64 a) {
    float x, y; upk2(a, x, y); return pk2(y, x);
}
__device__ __forceinline__ u64 ffma2(u64 a, u64 b, u64 c) {
    u64 d; asm("fma.rn.f32x2 %0, %1, %2, %3;" : "=l"(d) : "l"(a), "l"(b), "l"(c));
    return d;
}
__device__ __forceinline__ u64 fmul2(u64 a, u64 b) {
    u64 d; asm("mul.rn.f32x2 %0, %1, %2;" : "=l"(d) : "l"(a), "l"(b));
    return d;
}
__device__ __forceinline__ u64 shx(u64 v, int m)   { return __shfl_xor_sync(0xffffffffu, v, m); }
__device__ __forceinline__ u64 shi(u64 v, int src) { return __shfl_sync(0xffffffffu, v, src); }

// complex scalar (mr,mi) times packed z: mr*z + (-mi,mi).*swp(z)
__device__ __forceinline__ u64 cmul_acc(float mr, float mi, u64 z, u64 acc) {
    return ffma2(pk2(-mi, mi), swp(z), ffma2(bcast(mr), z, acc));
}
__device__ __forceinline__ u64 cmul(float mr, float mi, u64 z) {
    return ffma2(pk2(-mi, mi), swp(z), fmul2(bcast(mr), z));
}

// ------------------------------ gates --------------------------------------

// RY(t): real rotation, componentwise
template<int W>
__device__ __forceinline__ void g_ry(u64 (&s)[16], float c, float sn, int lane) {
    if constexpr (W >= 5) {
        constexpr int M = 1 << (8 - W);
        u64 Cc = bcast(c), Sp = bcast(sn), Sm = bcast(-sn);
#pragma unroll
        for (int r = 0; r < 16; r++) if (!(r & M)) {
            u64 a = s[r], b = s[r | M];
            s[r]     = ffma2(Sm, b, fmul2(Cc, a));
            s[r | M] = ffma2(Sp, a, fmul2(Cc, b));
        }
    } else {
        constexpr int LM = 1 << (4 - W);
        u64 Cc = bcast(c), Bs = bcast((lane & LM) ? sn : -sn);
#pragma unroll
        for (int r = 0; r < 16; r++) {
            u64 p = shx(s[r], LM);
            s[r] = ffma2(Bs, p, fmul2(Cc, s[r]));
        }
    }
}

// CNOT control C target T (used by SEL layers)
template<int C, int T>
__device__ __forceinline__ void g_cnot(u64 (&s)[16], int lane) {
    if constexpr (C >= 5 && T >= 5) {
        constexpr int MC = 1 << (8 - C), MT = 1 << (8 - T);
#pragma unroll
        for (int r = 0; r < 16; r++) if ((r & MC) && !(r & MT)) {
            u64 t = s[r]; s[r] = s[r | MT]; s[r | MT] = t;
        }
    } else if constexpr (C >= 5) {           // T low
        constexpr int MC = 1 << (8 - C), LMT = 1 << (4 - T);
#pragma unroll
        for (int r = 0; r < 16; r++) if (r & MC) s[r] = shx(s[r], LMT);
    } else if constexpr (T >= 5) {           // C low
        constexpr int LMC = 1 << (4 - C), MT = 1 << (8 - T);
        bool cb = (lane & LMC) != 0;
#pragma unroll
        for (int r = 0; r < 16; r++) if (!(r & MT)) {
            u64 a = s[r], b = s[r | MT];
            s[r]      = cb ? b : a;
            s[r | MT] = cb ? a : b;
        }
    } else {                                  // both low: single variable shuffle
        constexpr int LMC = 1 << (4 - C), LMT = 1 << (4 - T);
        int src = lane ^ ((lane & LMC) ? LMT : 0);
#pragma unroll
        for (int r = 0; r < 16; r++) s[r] = shi(s[r], src);
    }
}

// Fused W = CRX * X * CRZ * CNOT * RY(ip)  on (C, T=ip).
// Block-diagonal in control bit:
//   c=0: W0 = X*RY(b) = [[sb, cb],[cb,-sb]]   (real)
//   c=1: W1 = RX(x)*diag(f,e)*RY(b)           (complex, precomputed)
// m layout: m[0]=sb, m[1]=cb, m[2..9] = w00r,w00i,w01r,w01i,w10r,w10i,w11r,w11i
template<int C, int T>
__device__ __forceinline__ void g_W(u64 (&s)[16], const float* m, int lane) {
    float sb = m[0], cb = m[1];
    if constexpr (C < 5 && T < 5) {
        constexpr int LMC = 1 << (4 - C), LMT = 1 << (4 - T);
        bool cbit = (lane & LMC) != 0;
        bool tbit = (lane & LMT) != 0;
        // out(self) = A*self + B*partner,  A = M[t][t],  B = M[t][t^1]
        float Ar = cbit ? (tbit ? m[8] : m[2]) : (tbit ? -sb : sb);
        float Ai = cbit ? (tbit ? m[9] : m[3]) : 0.f;
        float Br = cbit ? (tbit ? m[6] : m[4]) : cb;
        float Bi = cbit ? (tbit ? m[7] : m[5]) : 0.f;
        u64 AR = bcast(Ar), AI = pk2(-Ai, Ai);
        u64 BR = bcast(Br), BI = pk2(-Bi, Bi);
#pragma unroll
        for (int r = 0; r < 16; r++) {
            u64 a = s[r];
            u64 p = shx(a, LMT);
            s[r] = ffma2(BI, swp(p), ffma2(BR, p, ffma2(AI, swp(a), fmul2(AR, a))));
        }
    } else if constexpr (C < 5 && T >= 5) {
        constexpr int LMC = 1 << (4 - C), MT = 1 << (8 - T);
        bool cbit = (lane & LMC) != 0;
        float m00r = cbit ? m[2] :  sb, m00i = cbit ? m[3] : 0.f;
        float m01r = cbit ? m[4] :  cb, m01i = cbit ? m[5] : 0.f;
        float m10r = cbit ? m[6] :  cb, m10i = cbit ? m[7] : 0.f;
        float m11r = cbit ? m[8] : -sb, m11i = cbit ? m[9] : 0.f;
#pragma unroll
        for (int r = 0; r < 16; r++) if (!(r & MT)) {
            u64 a = s[r], b = s[r | MT];
            s[r]      = cmul_acc(m01r, m01i, b, cmul(m00r, m00i, a));
            s[r | MT] = cmul_acc(m11r, m11i, b, cmul(m10r, m10i, a));
        }
    } else if constexpr (C >= 5 && T < 5) {
        constexpr int MC = 1 << (8 - C), LMT = 1 << (4 - T);
        bool tbit = (lane & LMT) != 0;
        // c=0 (real): A0 = tbit? -sb: sb, B0 = cb
        u64 A0 = bcast(tbit ? -sb : sb), B0 = bcast(cb);
        // c=1 (complex)
        float Ar = tbit ? m[8] : m[2], Ai = tbit ? m[9] : m[3];
        float Br = tbit ? m[6] : m[4], Bi = tbit ? m[7] : m[5];
        u64 AR = bcast(Ar), AI = pk2(-Ai, Ai);
        u64 BR = bcast(Br), BI = pk2(-Bi, Bi);
#pragma unroll
        for (int r = 0; r < 16; r++) {
            u64 a = s[r];
            u64 p = shx(a, LMT);
            if (r & MC)
                s[r] = ffma2(BI, swp(p), ffma2(BR, p, ffma2(AI, swp(a), fmul2(AR, a))));
            else
                s[r] = ffma2(B0, p, fmul2(A0, a));
        }
    } else {   // C >= 5 && T >= 5
        constexpr int MC = 1 << (8 - C), MT = 1 << (8 - T);
        u64 SB = bcast(sb), SBn = bcast(-sb), CB = bcast(cb);
#pragma unroll
        for (int r = 0; r < 16; r++) if (!(r & MT)) {
            u64 a = s[r], b = s[r | MT];
            if (r & MC) {
                s[r]      = cmul_acc(m[4], m[5], b, cmul(m[2], m[3], a));
                s[r | MT] = cmul_acc(m[8], m[9], b, cmul(m[6], m[7], a));
            } else {
                s[r]      = ffma2(CB, b, fmul2(SB, a));
                s[r | MT] = ffma2(SBn, b, fmul2(CB, a));
            }
        }
    }
}

// Generic complex 2x2 (Rot). o: u00r,u00i,u01r,u01i,u10r,u10i,u11r,u11i
template<int W>
__device__ __forceinline__ void g_rot(u64 (&s)[16], const float* o, int lane) {
    if constexpr (W >= 5) {
        constexpr int M = 1 << (8 - W);
#pragma unroll
        for (int r = 0; r < 16; r++) if (!(r & M)) {
            u64 a = s[r], b = s[r | M];
            u64 na = cmul_acc(o[2], o[3], b, cmul(o[0], o[1], a));
            u64 nb = cmul_acc(o[6], o[7], b, cmul(o[4], o[5], a));
            s[r] = na; s[r | M] = nb;
        }
    } else {
        constexpr int LM = 1 << (4 - W);
        bool bit = (lane & LM) != 0;
        float Ar = bit ? o[6] : o[0], Ai = bit ? o[7] : o[1];
        float Br = bit ? o[4] : o[2], Bi = bit ? o[5] : o[3];
        u64 ARe = bcast(Ar), AIm = pk2(-Ai, Ai);
        u64 BRe = bcast(Br), BIm = pk2(-Bi, Bi);
#pragma unroll
        for (int r = 0; r < 16; r++) {
            u64 a = s[r];
            u64 p = shx(a, LM);
            s[r] = ffma2(BIm, swp(p), ffma2(BRe, p, ffma2(AIm, swp(a), fmul2(ARe, a))));
        }
    }
}

// One entangle step i: RY(i) then fused W on (i, ip)
__device__ __forceinline__ void ent_block(u64 (&s)[16], const float* cf, int lane) {
    static_for<9>([&](auto ic) {
        constexpr int I  = decltype(ic)::value;
        constexpr int IP = (I + 1) % 9;
        const float* m = cf + I * ENT_STRIDE;
        g_ry<I>(s, m[0], m[1], lane);
        g_W<I, IP>(s, m + 2, lane);
    });
}

// ------------------------- coefficient prep kernel -------------------------
__global__ void prep_kernel(const float* __restrict__ params,
                            const float* __restrict__ weights,
                            const float* __restrict__ params2) {
    int t = threadIdx.x;
    if (t < 72) {
        int b = t / 9, i = t % 9;
        const float* p = (b < 3) ? (params + b * 36 + i * 4)
                                 : (params2 + (b - 3) * 36 + i * 4);
        float* o = g_coef + t * ENT_STRIDE;
        float ca, sa; sincosf(0.5f * p[0], &sa, &ca);   // RY(i)
        float cb, sb; sincosf(0.5f * p[1], &sb, &cb);   // RY(ip)
        float cz, sz; sincosf(0.5f * p[2], &sz, &cz);   // CRZ
        float cx, sx; sincosf(0.5f * p[3], &sx, &cx);   // CRX
        o[0] = ca; o[1] = sa;
        o[2] = sb; o[3] = cb;
        // D = diag(f,e)*RY(b),  f=(cz,sz), e=(cz,-sz)
        float d00r =  cz * cb, d00i =  sz * cb;
        float d01r = -cz * sb, d01i = -sz * sb;
        float d10r =  cz * sb, d10i = -sz * sb;
        float d11r =  cz * cb, d11i = -sz * cb;
        // W1 = RX(x)*D ; RX row0 = (cx, -i sx), row1 = (-i sx, cx)
        // (-i sx)*(zr,zi) = (sx*zi, -sx*zr)
        o[4]  = cx * d00r + sx * d10i;  o[5]  = cx * d00i - sx * d10r;  // w00
        o[6]  = cx * d01r + sx * d11i;  o[7]  = cx * d01i - sx * d11r;  // w01
        o[8]  = sx * d00i + cx * d10r;  o[9]  = -sx * d00r + cx * d10i; // w10
        o[10] = sx * d01i + cx * d11r;  o[11] = -sx * d01r + cx * d11i; // w11
    } else if (t < 99) {
        int idx = t - 72;
        int l = idx / 9, i = idx % 9;
        const float* w = weights + (l * 9 + i) * 3;
        float phi = w[0], th = w[1], om = w[2];
        float ct, st; sincosf(0.5f * th, &st, &ct);
        float aa = 0.5f * (phi + om), bb = 0.5f * (phi - om);
        float ca, sa; sincosf(aa, &sa, &ca);
        float cb, sb; sincosf(bb, &sb, &cb);
        float* o = g_coef + ROT_OFF + idx * 8;
        o[0] =  ct * ca; o[1] = -ct * sa;   // u00
        o[2] = -st * cb; o[3] = -st * sb;   // u01
        o[4] =  st * cb; o[5] = -st * sb;   // u10
        o[6] =  ct * ca; o[7] =  ct * sa;   // u11
    }
}

// ------------------------------- sim kernel --------------------------------
__global__ void __launch_bounds__(128, 6)
sim_kernel(const float* __restrict__ adds, float* __restrict__ out, int B) {
    __shared__ float sh[N_COEF];
    for (int i = threadIdx.x; i < N_COEF; i += blockDim.x) sh[i] = g_coef[i];
    __syncthreads();

    int lane = threadIdx.x & 31;
    int item = blockIdx.x * (blockDim.x >> 5) + (threadIdx.x >> 5);
    if (item >= B) return;

    // per-sample embedding angles: lane w (<9) computes sincos for wire w
    float ec = 1.f, es = 0.f;
    if (lane < 9) {
        float a = adds[item * 9 + lane];
        sincosf(0.5f * a, &es, &ec);
    }
    // broadcast all 9 (c,s) pairs to every lane
    float cw[9], sw[9];
#pragma unroll
    for (int w = 0; w < 9; w++) {
        cw[w] = __shfl_sync(0xffffffffu, ec, w);
        sw[w] = __shfl_sync(0xffffffffu, es, w);
    }

    // Direct tensor-product init: amp(idx) = prod_w (bit? -i*s_w : c_w)
    //   = mag * (-i)^popc(idx)
    // lane bits: wire w<5 <-> lane bit (4-w); reg bits: wire w>=5 <-> reg bit (8-w)
    float magl = 1.f;
#pragma unroll
    for (int w = 0; w < 5; w++)
        magl *= (lane & (1 << (4 - w))) ? sw[w] : cw[w];
    int klane = __popc(lane);

    u64 s[16];
    static_for<16>([&](auto rc) {
        constexpr int R = decltype(rc)::value;
        float mr = ((R & 8) ? sw[5] : cw[5]) * ((R & 4) ? sw[6] : cw[6])
                 * ((R & 2) ? sw[7] : cw[7]) * ((R & 1) ? sw[8] : cw[8]);
        float v = magl * mr;
        constexpr int KR = ((R >> 3) & 1) + ((R >> 2) & 1) + ((R >> 1) & 1) + (R & 1);
        int k = (klane + KR) & 3;
        float re = (k == 0) ? v : (k == 2) ? -v : 0.f;
        float im = (k == 1) ? -v : (k == 3) ? v : 0.f;
        s[R] = pk2(re, im);
    });

    // 3 QRAM entangle blocks
    for (int b = 0; b < 3; b++) ent_block(s, sh + b * 9 * ENT_STRIDE, lane);

    // 3 StronglyEntanglingLayers (range r = L+1)
    static_for<3>([&](auto lc) {
        constexpr int L = decltype(lc)::value;
        static_for<9>([&](auto ic) {
            constexpr int I = decltype(ic)::value;
            g_rot<I>(s, sh + ROT_OFF + (L * 9 + I) * 8, lane);
        });
        static_for<9>([&](auto ic) {
            constexpr int I = decltype(ic)::value;
            g_cnot<I, (I + L + 1) % 9>(s, lane);
        });
    });

    // 5 classifier entangle blocks
    for (int b = 3; b < 8; b++) ent_block(s, sh + b * 9 * ENT_STRIDE, lane);

    // <Z0>: wire 0 = lane bit 4
    float acc = 0.f;
#pragma unroll
    for (int r = 0; r < 16; r++) {
        float x, y; upk2(s[r], x, y);
        acc += x * x + y * y;
    }
    if (lane & 16) acc = -acc;
#pragma unroll
    for (int m = 16; m >= 1; m >>= 1) acc += __shfl_xor_sync(0xffffffffu, acc, m);
    if (lane == 0) out[item] = acc;
}

// ------------------------------ launcher -----------------------------------
extern "C" void kernel_launch(void* const* d_in, const int* in_sizes, int n_in,
                              void* d_out, int out_size) {
    const float* adds    = (const float*)d_in[0];
    const float* params  = (const float*)d_in[1];
    const float* weights = (const float*)d_in[2];
    const float* params2 = (const float*)d_in[3];
    float* out = (float*)d_out;

    int B = in_sizes[0] / 9;

    prep_kernel<<<1, 128>>>(params, weights, params2);

    int warpsPerBlock = 4;
    int blocks = (B + warpsPerBlock - 1) / warpsPerBlock;
    sim_kernel<<<blocks, 128>>>(adds, out, B);
}

// round 8
// speedup vs baseline: 1.8818x; 1.0030x over previous
#include <cuda_runtime.h>
#include <cuda_bf16.h>

// ---------------------------------------------------------------------------
// 9-wire statevector simulator. One warp per batch item, 16 complex amps/lane,
// amplitudes PACKED (re,im) in 64-bit regs, gate math via f32x2 FMA.
// Amplitude index idx[8:0]: wire w <-> bit (8-w).
//   wires 0..4  -> lane bits 4..0   (shuffles)
//   wires 5..8  -> reg  bits 3..0   (register ops)
//
// R6: full adjacent-gate fusion. All RY/Rot 1q gates absorbed into the
// neighboring controlled 2-qubit gates -> 99 generic controlled-2x2 gates
// (+2 standalone Rots), matrices precomputed by prep_kernel.
// ---------------------------------------------------------------------------

using u64 = unsigned long long;

#define N_GATES 99
#define R1OFF   (N_GATES * 16)        // standalone Rot(L1, wire1)
#define R2OFF   (R1OFF + 8)           // standalone Rot(L2, wire2)
#define RY0OFF  (R2OFF + 8)           // (ca, sa) of RY_0^{(block0)}
#define N_COEF  (RY0OFF + 2)          // 1602 floats
__device__ float g_coef[N_COEF];

template<int V> struct IC { static constexpr int value = V; };
template<int N, typename F>
__device__ __forceinline__ void static_for(F&& f) {
    if constexpr (N > 0) { static_for<N - 1>(f); f(IC<N - 1>{}); }
}

// ------------------------- packed f32x2 helpers ----------------------------
__device__ __forceinline__ u64 pk2(float lo, float hi) {
    u64 r;
    asm("mov.b64 %0, {%1, %2};" : "=l"(r)
        : "r"(__float_as_uint(lo)), "r"(__float_as_uint(hi)));
    return r;
}
__device__ __forceinline__ void upk2(u64 a, float& lo, float& hi) {
    unsigned l_, h_;
    asm("mov.b64 {%0, %1}, %2;" : "=r"(l_), "=r"(h_) : "l"(a));
    lo = __uint_as_float(l_); hi = __uint_as_float(h_);
}
__device__ __forceinline__ u64 bcast(float x) { return pk2(x, x); }
__device__ __forceinline__ u64 swp(u64 a) {
    float x, y; upk2(a, x, y); return pk2(y, x);
}
__device__ __forceinline__ u64 ffma2(u64 a, u64 b, u64 c) {
    u64 d; asm("fma.rn.f32x2 %0, %1, %2, %3;" : "=l"(d) : "l"(a), "l"(b), "l"(c));
    return d;
}
__device__ __forceinline__ u64 fmul2(u64 a, u64 b) {
    u64 d; asm("mul.rn.f32x2 %0, %1, %2;" : "=l"(d) : "l"(a), "l"(b));
    return d;
}
__device__ __forceinline__ u64 shx(u64 v, int m) { return __shfl_xor_sync(0xffffffffu, v, m); }

// complex scalar (mr,mi) times packed z, optionally accumulating
__device__ __forceinline__ u64 cmul_acc(float mr, float mi, u64 z, u64 acc) {
    return ffma2(pk2(-mi, mi), swp(z), ffma2(bcast(mr), z, acc));
}
__device__ __forceinline__ u64 cmul(float mr, float mi, u64 z) {
    return ffma2(pk2(-mi, mi), swp(z), fmul2(bcast(mr), z));
}

// ------------------------------ gates --------------------------------------

// Generic controlled 2x2: m[0..7] = M0 (control=0), m[8..15] = M1 (control=1),
// each 00r,00i,01r,01i,10r,10i,11r,11i.
template<int C, int T>
__device__ __forceinline__ void g_c2x2(u64 (&s)[16], const float* m, int lane) {
    if constexpr (T < 5) {
        constexpr int LMT = 1 << (4 - T);
        bool tbit = (lane & LMT) != 0;
        if constexpr (C < 5) {
            constexpr int LMC = 1 << (4 - C);
            const float* mm = (lane & LMC) ? m + 8 : m;
            float Ar = tbit ? mm[6] : mm[0], Ai = tbit ? mm[7] : mm[1];
            float Br = tbit ? mm[4] : mm[2], Bi = tbit ? mm[5] : mm[3];
            u64 AR = bcast(Ar), AI = pk2(-Ai, Ai);
            u64 BR = bcast(Br), BI = pk2(-Bi, Bi);
#pragma unroll
            for (int r = 0; r < 16; r++) {
                u64 a = s[r], p = shx(a, LMT);
                s[r] = ffma2(BI, swp(p), ffma2(BR, p, ffma2(AI, swp(a), fmul2(AR, a))));
            }
        } else {
            constexpr int MC = 1 << (8 - C);
            float A0r = tbit ? m[6]  : m[0],  A0i = tbit ? m[7]  : m[1];
            float B0r = tbit ? m[4]  : m[2],  B0i = tbit ? m[5]  : m[3];
            float A1r = tbit ? m[14] : m[8],  A1i = tbit ? m[15] : m[9];
            float B1r = tbit ? m[12] : m[10], B1i = tbit ? m[13] : m[11];
            u64 AR0 = bcast(A0r), AI0 = pk2(-A0i, A0i);
            u64 BR0 = bcast(B0r), BI0 = pk2(-B0i, B0i);
            u64 AR1 = bcast(A1r), AI1 = pk2(-A1i, A1i);
            u64 BR1 = bcast(B1r), BI1 = pk2(-B1i, B1i);
#pragma unroll
            for (int r = 0; r < 16; r++) {
                u64 a = s[r], p = shx(a, LMT);
                if (r & MC)
                    s[r] = ffma2(BI1, swp(p), ffma2(BR1, p, ffma2(AI1, swp(a), fmul2(AR1, a))));
                else
                    s[r] = ffma2(BI0, swp(p), ffma2(BR0, p, ffma2(AI0, swp(a), fmul2(AR0, a))));
            }
        }
    } else {
        constexpr int MT = 1 << (8 - T);
        if constexpr (C < 5) {
            constexpr int LMC = 1 << (4 - C);
            const float* mm = (lane & LMC) ? m + 8 : m;
            float m00r = mm[0], m00i = mm[1], m01r = mm[2], m01i = mm[3];
            float m10r = mm[4], m10i = mm[5], m11r = mm[6], m11i = mm[7];
#pragma unroll
            for (int r = 0; r < 16; r++) if (!(r & MT)) {
                u64 a = s[r], b = s[r | MT];
                s[r]      = cmul_acc(m01r, m01i, b, cmul(m00r, m00i, a));
                s[r | MT] = cmul_acc(m11r, m11i, b, cmul(m10r, m10i, a));
            }
        } else {
            constexpr int MC = 1 << (8 - C);
            // two half-loops to limit coefficient liveness
#pragma unroll
            for (int r = 0; r < 16; r++) if (!(r & MT) && !(r & MC)) {
                u64 a = s[r], b = s[r | MT];
                s[r]      = cmul_acc(m[2], m[3], b, cmul(m[0], m[1], a));
                s[r | MT] = cmul_acc(m[6], m[7], b, cmul(m[4], m[5], a));
            }
#pragma unroll
            for (int r = 0; r < 16; r++) if (!(r & MT) && (r & MC)) {
                u64 a = s[r], b = s[r | MT];
                s[r]      = cmul_acc(m[10], m[11], b, cmul(m[8],  m[9],  a));
                s[r | MT] = cmul_acc(m[14], m[15], b, cmul(m[12], m[13], a));
            }
        }
    }
}

// Plain 1q complex 2x2 (standalone Rots; wires 1,2 are lane wires)
template<int W>
__device__ __forceinline__ void g_rot(u64 (&s)[16], const float* o, int lane) {
    if constexpr (W >= 5) {
        constexpr int M = 1 << (8 - W);
#pragma unroll
        for (int r = 0; r < 16; r++) if (!(r & M)) {
            u64 a = s[r], b = s[r | M];
            u64 na = cmul_acc(o[2], o[3], b, cmul(o[0], o[1], a));
            u64 nb = cmul_acc(o[6], o[7], b, cmul(o[4], o[5], a));
            s[r] = na; s[r | M] = nb;
        }
    } else {
        constexpr int LM = 1 << (4 - W);
        bool bit = (lane & LM) != 0;
        float Ar = bit ? o[6] : o[0], Ai = bit ? o[7] : o[1];
        float Br = bit ? o[4] : o[2], Bi = bit ? o[5] : o[3];
        u64 ARe = bcast(Ar), AIm = pk2(-Ai, Ai);
        u64 BRe = bcast(Br), BIm = pk2(-Bi, Bi);
#pragma unroll
        for (int r = 0; r < 16; r++) {
            u64 a = s[r], p = shx(a, LM);
            s[r] = ffma2(BIm, swp(p), ffma2(BRe, p, ffma2(AIm, swp(a), fmul2(ARe, a))));
        }
    }
}

// ------------------------- prep: complex 2x2 algebra -----------------------
struct cpx { float r, i; };
__device__ __forceinline__ cpx cmulh(cpx x, cpx y) {
    return { x.r * y.r - x.i * y.i, x.r * y.i + x.i * y.r };
}
__device__ __forceinline__ cpx caddh(cpx x, cpx y) { return { x.r + y.r, x.i + y.i }; }
struct mat2 { cpx m00, m01, m10, m11; };
__device__ mat2 mmul(mat2 A, mat2 B) {
    return { caddh(cmulh(A.m00, B.m00), cmulh(A.m01, B.m10)),
             caddh(cmulh(A.m00, B.m01), cmulh(A.m01, B.m11)),
             caddh(cmulh(A.m10, B.m00), cmulh(A.m11, B.m10)),
             caddh(cmulh(A.m10, B.m01), cmulh(A.m11, B.m11)) };
}
__device__ mat2 mI() { return { {1,0},{0,0},{0,0},{1,0} }; }
__device__ mat2 mX() { return { {0,0},{1,0},{1,0},{0,0} }; }
__device__ mat2 mRY(float t) {
    float c, s; sincosf(0.5f * t, &s, &c);
    return { {c,0},{-s,0},{s,0},{c,0} };
}
__device__ mat2 mRot(const float* w) {
    float phi = w[0], th = w[1], om = w[2];
    float ct, st; sincosf(0.5f * th, &st, &ct);
    float ca, sa; sincosf(0.5f * (phi + om), &sa, &ca);
    float cb, sb; sincosf(0.5f * (phi - om), &sb, &cb);
    return { { ct * ca, -ct * sa }, { -st * cb, -st * sb },
             { st * cb, -st * sb }, { ct * ca,  ct * sa } };
}
// K c=0 block: X*RY(b)
__device__ mat2 mK0(float pb) {
    float cb, sb; sincosf(0.5f * pb, &sb, &cb);
    return { {sb,0},{cb,0},{cb,0},{-sb,0} };
}
// K c=1 block: RX(x)*diag(f,e)*RY(b), f=(cz,sz), e=(cz,-sz)
__device__ mat2 mK1(float pb, float pz, float px) {
    float cb, sb; sincosf(0.5f * pb, &sb, &cb);
    float cz, sz; sincosf(0.5f * pz, &sz, &cz);
    float cx, sx; sincosf(0.5f * px, &sx, &cx);
    float d00r =  cz * cb, d00i =  sz * cb;
    float d01r = -cz * sb, d01i = -sz * sb;
    float d10r =  cz * sb, d10i = -sz * sb;
    float d11r =  cz * cb, d11i = -sz * cb;
    mat2 W;
    W.m00 = {  cx * d00r + sx * d10i,  cx * d00i - sx * d10r };
    W.m01 = {  cx * d01r + sx * d11i,  cx * d01i - sx * d11r };
    W.m10 = {  sx * d00i + cx * d10r, -sx * d00r + cx * d10i };
    W.m11 = {  sx * d01i + cx * d11r, -sx * d01r + cx * d11i };
    return W;
}
__device__ void store8(float* o, mat2 M) {
    o[0] = M.m00.r; o[1] = M.m00.i; o[2] = M.m01.r; o[3] = M.m01.i;
    o[4] = M.m10.r; o[5] = M.m10.i; o[6] = M.m11.r; o[7] = M.m11.i;
}

// ------------------------- coefficient prep kernel -------------------------
// Gate slots (application order):
//   0..26   QRAM blocks b=0..2, step i      (C=i, T=(i+1)%9)
//   27..35  SEL L0 (r=1), i                 (C=i, T=(i+1)%9)
//   36..44  SEL L1 (r=2), i                 (C=i, T=(i+2)%9)
//   45..53  SEL L2 (r=3), i                 (C=i, T=(i+3)%9)
//   54..98  classifier blocks b=3..7, step i
__global__ void prep_kernel(const float* __restrict__ params,
                            const float* __restrict__ weights,
                            const float* __restrict__ params2) {
    int t = threadIdx.x;
    if ((t < 27) || (t >= 54 && t < 99)) {
        // entangle-block fused gate Wf_i^{(b)}
        int b = (t < 27) ? t / 9 : 3 + (t - 54) / 9;
        int i = (t < 27) ? t % 9 : (t - 54) % 9;
        const float* pb_ = (b < 3) ? params + b * 36 : params2 + (b - 3) * 36;
        float bb = pb_[i * 4 + 1], zz = pb_[i * 4 + 2], xx = pb_[i * 4 + 3];
        mat2 M0 = mK0(bb), M1 = mK1(bb, zz, xx);
        mat2 U;
        if (i < 8) {
            U = mRY(pb_[(i + 1) * 4 + 0]);                 // next step's RY(a) on wire i+1
        } else if (b == 2) {
            U = mRot(weights + 0);                          // Rot_0^{L0}
        } else if (b == 7) {
            U = mI();                                       // final gate
        } else {
            const float* nb = (b + 1 < 3) ? params + (b + 1) * 36
                                          : params2 + (b + 1 - 3) * 36;
            U = mRY(nb[0]);                                 // next block's RY(a_0)
        }
        M0 = mmul(U, M0); M1 = mmul(U, M1);
        float* o = g_coef + t * 16;
        store8(o, M0); store8(o + 8, M1);
    } else if (t >= 27 && t < 54) {
        // SEL fused CNOT: M0 = Lt*R ; M1 = Lt*X*R
        int L = (t - 27) / 9, i = (t - 27) % 9, r = L + 1;
        int tt = (i + r) % 9;
        mat2 R = mI(), Lt = mI();
        if (L == 0 && i < 8) R = mRot(weights + (0 * 9 + tt) * 3);
        if (L == 1 && i < 7) R = mRot(weights + (1 * 9 + tt) * 3);
        if (L == 2 && i < 6) R = mRot(weights + (2 * 9 + tt) * 3);
        if (L == 0 && i == 8) Lt = mRot(weights + (1 * 9 + 0) * 3);   // Rot_0^{L1}
        if (L == 1 && i == 7) Lt = mRot(weights + (2 * 9 + 0) * 3);   // Rot_0^{L2}
        if (L == 1 && i == 8) Lt = mRot(weights + (2 * 9 + 1) * 3);   // Rot_1^{L2}
        if (L == 2 && i == 6) Lt = mRY(params2[0]);                   // RY_0^{(block3)}
        mat2 M0 = mmul(Lt, R);
        mat2 M1 = mmul(Lt, mmul(mX(), R));
        float* o = g_coef + t * 16;
        store8(o, M0); store8(o + 8, M1);
    } else if (t == 99) {
        store8(g_coef + R1OFF, mRot(weights + (1 * 9 + 1) * 3));      // Rot_1^{L1}
    } else if (t == 100) {
        store8(g_coef + R2OFF, mRot(weights + (2 * 9 + 2) * 3));      // Rot_2^{L2}
    } else if (t == 101) {
        float c, s; sincosf(0.5f * params[0], &s, &c);                // RY_0^{(0)}
        g_coef[RY0OFF] = c; g_coef[RY0OFF + 1] = s;
    }
}

// ------------------------------- sim kernel --------------------------------
__global__ void __launch_bounds__(128, 6)
sim_kernel(const float* __restrict__ adds, float* __restrict__ out, int B) {
    __shared__ float sh[N_COEF];
    for (int i = threadIdx.x; i < N_COEF; i += blockDim.x) sh[i] = g_coef[i];
    __syncthreads();

    int lane = threadIdx.x & 31;
    int item = blockIdx.x * (blockDim.x >> 5) + (threadIdx.x >> 5);
    if (item >= B) return;

    // per-sample embedding angles: lane w (<9) computes sincos for wire w
    float ec = 1.f, es = 0.f;
    if (lane < 9) {
        float a = adds[item * 9 + lane];
        sincosf(0.5f * a, &es, &ec);
    }
    float cw[9], sw[9];
#pragma unroll
    for (int w = 0; w < 9; w++) {
        cw[w] = __shfl_sync(0xffffffffu, ec, w);
        sw[w] = __shfl_sync(0xffffffffu, es, w);
    }

    // Init: RX embedding tensor product, with RY_0^{(0)} fused into wire-0 factor.
    // wires 1..4 -> lane bits 3..0; wire 0 -> lane bit 4; wires 5..8 -> reg bits 3..0
    float magl = ((lane & 8) ? sw[1] : cw[1]) * ((lane & 4) ? sw[2] : cw[2])
               * ((lane & 2) ? sw[3] : cw[3]) * ((lane & 1) ? sw[4] : cw[4]);
    int klane = __popc(lane & 15);
    bool b0 = (lane & 16) != 0;
    float ca0 = sh[RY0OFF], sa0 = sh[RY0OFF + 1];
    // v0 = RY(a0) * (c0, -i s0); select component by wire-0 bit
    float v0r = b0 ? sa0 * cw[0] : ca0 * cw[0];
    float v0i = b0 ? -ca0 * sw[0] : sa0 * sw[0];

    u64 s[16];
    static_for<16>([&](auto rc) {
        constexpr int R = decltype(rc)::value;
        float mr = ((R & 8) ? sw[5] : cw[5]) * ((R & 4) ? sw[6] : cw[6])
                 * ((R & 2) ? sw[7] : cw[7]) * ((R & 1) ? sw[8] : cw[8]);
        float v = magl * mr;
        constexpr int KR = ((R >> 3) & 1) + ((R >> 2) & 1) + ((R >> 1) & 1) + (R & 1);
        int k = (klane + KR) & 3;
        // amp = v * (-i)^k * (v0r + i v0i)
        float re = (k == 0) ?  v * v0r : (k == 1) ?  v * v0i
                 : (k == 2) ? -v * v0r :            -v * v0i;
        float im = (k == 0) ?  v * v0i : (k == 1) ? -v * v0r
                 : (k == 2) ? -v * v0i :             v * v0r;
        s[R] = pk2(re, im);
    });

    // QRAM blocks 0..2
    static_for<3>([&](auto bc) {
        constexpr int Bb = decltype(bc)::value;
        static_for<9>([&](auto ic) {
            constexpr int I = decltype(ic)::value;
            g_c2x2<I, (I + 1) % 9>(s, sh + (Bb * 9 + I) * 16, lane);
        });
    });

    // SEL L0
    static_for<9>([&](auto ic) {
        constexpr int I = decltype(ic)::value;
        g_c2x2<I, (I + 1) % 9>(s, sh + (27 + I) * 16, lane);
    });
    g_rot<1>(s, sh + R1OFF, lane);
    // SEL L1
    static_for<9>([&](auto ic) {
        constexpr int I = decltype(ic)::value;
        g_c2x2<I, (I + 2) % 9>(s, sh + (36 + I) * 16, lane);
    });
    g_rot<2>(s, sh + R2OFF, lane);
    // SEL L2
    static_for<9>([&](auto ic) {
        constexpr int I = decltype(ic)::value;
        g_c2x2<I, (I + 3) % 9>(s, sh + (45 + I) * 16, lane);
    });

    // classifier blocks 3..7
    static_for<5>([&](auto bc) {
        constexpr int Bb = decltype(bc)::value;
        static_for<9>([&](auto ic) {
            constexpr int I = decltype(ic)::value;
            g_c2x2<I, (I + 1) % 9>(s, sh + (54 + Bb * 9 + I) * 16, lane);
        });
    });

    // <Z0>: wire 0 = lane bit 4
    float acc = 0.f;
#pragma unroll
    for (int r = 0; r < 16; r++) {
        float x, y; upk2(s[r], x, y);
        acc += x * x + y * y;
    }
    if (lane & 16) acc = -acc;
#pragma unroll
    for (int m = 16; m >= 1; m >>= 1) acc += __shfl_xor_sync(0xffffffffu, acc, m);
    if (lane == 0) out[item] = acc;
}

// ------------------------------ launcher -----------------------------------
extern "C" void kernel_launch(void* const* d_in, const int* in_sizes, int n_in,
                              void* d_out, int out_size) {
    const float* adds    = (const float*)d_in[0];
    const float* params  = (const float*)d_in[1];
    const float* weights = (const float*)d_in[2];
    const float* params2 = (const float*)d_in[3];
    float* out = (float*)d_out;

    int B = in_sizes[0] / 9;

    prep_kernel<<<1, 128>>>(params, weights, params2);

    int warpsPerBlock = 4;
    int blocks = (B + warpsPerBlock - 1) / warpsPerBlock;
    sim_kernel<<<blocks, 128>>>(adds, out, B);
}

// round 10
// speedup vs baseline: 2.0646x; 1.0971x over previous
#include <cuda_runtime.h>
#include <cuda_bf16.h>

// ---------------------------------------------------------------------------
// 9-wire statevector simulator. One warp per batch item, 16 complex amps/lane.
// R8: SoA f32x2 packing — u64 re[8]/im[8] hold (component of amp q, amp q+8),
// pairing along reg bit 3 (= wire 5). Complex gate math is fully
// componentwise (no operand swaps); gates controlled on wire 5 are free.
// Coefficient prep (gate fusion) is done per-block into shared memory
// (single kernel, no separate prep launch).
//
// Amplitude index idx[8:0]: wire w <-> bit (8-w).
//   wires 0..4 -> lane bits 4..0 (shuffles)
//   wire  5    -> f32x2 packed half
//   wires 6..8 -> reg bits 2..0 of q
// ---------------------------------------------------------------------------

using u64 = unsigned long long;

#define N_GATES 99
#define R1OFF   (N_GATES * 16)        // standalone Rot(L1, wire1)
#define R2OFF   (R1OFF + 8)           // standalone Rot(L2, wire2)
#define RY0OFF  (R2OFF + 8)           // (ca, sa) of RY_0^{(block0)}
#define N_COEF  (RY0OFF + 2)          // 1602 floats

template<int V> struct IC { static constexpr int value = V; };
template<int N, typename F>
__device__ __forceinline__ void static_for(F&& f) {
    if constexpr (N > 0) { static_for<N - 1>(f); f(IC<N - 1>{}); }
}

// ------------------------- packed f32x2 helpers ----------------------------
__device__ __forceinline__ u64 pk2(float lo, float hi) {
    u64 r;
    asm("mov.b64 %0, {%1, %2};" : "=l"(r)
        : "r"(__float_as_uint(lo)), "r"(__float_as_uint(hi)));
    return r;
}
__device__ __forceinline__ void upk2(u64 a, float& lo, float& hi) {
    unsigned l_, h_;
    asm("mov.b64 {%0, %1}, %2;" : "=r"(l_), "=r"(h_) : "l"(a));
    lo = __uint_as_float(l_); hi = __uint_as_float(h_);
}
__device__ __forceinline__ u64 bcast(float x) { return pk2(x, x); }
__device__ __forceinline__ u64 swp(u64 a) {
    float x, y; upk2(a, x, y); return pk2(y, x);
}
__device__ __forceinline__ u64 ffma2(u64 a, u64 b, u64 c) {
    u64 d; asm("fma.rn.f32x2 %0, %1, %2, %3;" : "=l"(d) : "l"(a), "l"(b), "l"(c));
    return d;
}
__device__ __forceinline__ u64 fmul2(u64 a, u64 b) {
    u64 d; asm("mul.rn.f32x2 %0, %1, %2;" : "=l"(d) : "l"(a), "l"(b));
    return d;
}
__device__ __forceinline__ u64 shx(u64 v, int m) { return __shfl_xor_sync(0xffffffffu, v, m); }

// --------------------- coefficient bundles for gates -----------------------
// Lane-target: out(self) = A*self + B*partner  (A,B complex scalars per lane)
struct CoefAB { u64 Ar, Ai, nAi, Br, Bi, nBi; };
__device__ __forceinline__ CoefAB mkAB(float Ar, float Ai, float Br, float Bi) {
    return { bcast(Ar), bcast(Ai), bcast(-Ai), bcast(Br), bcast(Bi), bcast(-Bi) };
}
__device__ __forceinline__ void apply_AB(u64& re, u64& im, u64 pre, u64 pim, const CoefAB& c) {
    u64 nre = ffma2(c.Br, pre, ffma2(c.nBi, pim, ffma2(c.nAi, im, fmul2(c.Ar, re))));
    u64 nim = ffma2(c.Bi, pre, ffma2(c.Br, pim, ffma2(c.Ai, re, fmul2(c.Ar, im))));
    re = nre; im = nim;
}

// Packed-target (wire 5): P = pk2(m00,m11) diag, Q = pk2(m01,m10) cross
struct CoefPQ { u64 Pr, Pi, nPi, Qr, Qi, nQi; };
__device__ __forceinline__ CoefPQ mkPQ(const float* mm) {
    return { pk2(mm[0], mm[6]), pk2(mm[1], mm[7]), pk2(-mm[1], -mm[7]),
             pk2(mm[2], mm[4]), pk2(mm[3], mm[5]), pk2(-mm[3], -mm[5]) };
}
__device__ __forceinline__ void apply_PQ(u64& re, u64& im, const CoefPQ& c) {
    u64 sre = swp(re), sim = swp(im);
    u64 nre = ffma2(c.Qr, sre, ffma2(c.nQi, sim, ffma2(c.nPi, im, fmul2(c.Pr, re))));
    u64 nim = ffma2(c.Qi, sre, ffma2(c.Qr, sim, ffma2(c.Pi, re, fmul2(c.Pr, im))));
    re = nre; im = nim;
}

// Reg-target: full 2x2 complex matrix
struct CoefM { u64 r00, i00, n00, r01, i01, n01, r10, i10, n10, r11, i11, n11; };
__device__ __forceinline__ CoefM mkM(const float* mm) {
    return { bcast(mm[0]), bcast(mm[1]), bcast(-mm[1]),
             bcast(mm[2]), bcast(mm[3]), bcast(-mm[3]),
             bcast(mm[4]), bcast(mm[5]), bcast(-mm[5]),
             bcast(mm[6]), bcast(mm[7]), bcast(-mm[7]) };
}
// control = wire 5 (packed): lo half uses M0 (m), hi half M1 (m+8)
__device__ __forceinline__ CoefM mkM2(const float* m) {
    const float* a = m; const float* b = m + 8;
    return { pk2(a[0], b[0]), pk2(a[1], b[1]), pk2(-a[1], -b[1]),
             pk2(a[2], b[2]), pk2(a[3], b[3]), pk2(-a[3], -b[3]),
             pk2(a[4], b[4]), pk2(a[5], b[5]), pk2(-a[5], -b[5]),
             pk2(a[6], b[6]), pk2(a[7], b[7]), pk2(-a[7], -b[7]) };
}
__device__ __forceinline__ void apply_pair(u64& req, u64& imq, u64& rep, u64& imp, const CoefM& c) {
    u64 nreq = ffma2(c.r01, rep, ffma2(c.n01, imp, ffma2(c.n00, imq, fmul2(c.r00, req))));
    u64 nimq = ffma2(c.i01, rep, ffma2(c.r01, imp, ffma2(c.i00, req, fmul2(c.r00, imq))));
    u64 nrep = ffma2(c.r11, rep, ffma2(c.n11, imp, ffma2(c.n10, imq, fmul2(c.r10, req))));
    u64 nimp = ffma2(c.i11, rep, ffma2(c.r11, imp, ffma2(c.i10, req, fmul2(c.r10, imq))));
    req = nreq; imq = nimq; rep = nrep; imp = nimp;
}

// select A/B scalars from an 8-float matrix by target bit
#define SEL_AB(mm, TB, Ar, Ai, Br, Bi) \
    float Ar = (TB) ? (mm)[6] : (mm)[0], Ai = (TB) ? (mm)[7] : (mm)[1]; \
    float Br = (TB) ? (mm)[4] : (mm)[2], Bi = (TB) ? (mm)[5] : (mm)[3];

// ------------------------------ gate ---------------------------------------
// m[0..7] = M0 (control=0), m[8..15] = M1 (control=1)
template<int C, int T>
__device__ __forceinline__ void gate(u64 (&re)[8], u64 (&im)[8], const float* m, int lane) {
    if constexpr (T < 5) {
        constexpr int LMT = 1 << (4 - T);
        bool tbit = (lane & LMT) != 0;
        if constexpr (C < 5) {
            const float* mm = (lane & (1 << (4 - C))) ? m + 8 : m;
            SEL_AB(mm, tbit, Ar, Ai, Br, Bi);
            CoefAB c = mkAB(Ar, Ai, Br, Bi);
#pragma unroll
            for (int q = 0; q < 8; q++) {
                u64 pre = shx(re[q], LMT), pim = shx(im[q], LMT);
                apply_AB(re[q], im[q], pre, pim, c);
            }
        } else if constexpr (C == 5) {
            SEL_AB(m,     tbit, A0r, A0i, B0r, B0i);
            SEL_AB(m + 8, tbit, A1r, A1i, B1r, B1i);
            CoefAB c = { pk2(A0r, A1r), pk2(A0i, A1i), pk2(-A0i, -A1i),
                         pk2(B0r, B1r), pk2(B0i, B1i), pk2(-B0i, -B1i) };
#pragma unroll
            for (int q = 0; q < 8; q++) {
                u64 pre = shx(re[q], LMT), pim = shx(im[q], LMT);
                apply_AB(re[q], im[q], pre, pim, c);
            }
        } else {
            constexpr int MC = 1 << (8 - C);
            SEL_AB(m,     tbit, A0r, A0i, B0r, B0i);
            SEL_AB(m + 8, tbit, A1r, A1i, B1r, B1i);
            CoefAB c0 = mkAB(A0r, A0i, B0r, B0i);
            CoefAB c1 = mkAB(A1r, A1i, B1r, B1i);
#pragma unroll
            for (int q = 0; q < 8; q++) {
                u64 pre = shx(re[q], LMT), pim = shx(im[q], LMT);
                apply_AB(re[q], im[q], pre, pim, (q & MC) ? c1 : c0);
            }
        }
    } else if constexpr (T == 5) {
        if constexpr (C < 5) {
            const float* mm = (lane & (1 << (4 - C))) ? m + 8 : m;
            CoefPQ c = mkPQ(mm);
#pragma unroll
            for (int q = 0; q < 8; q++) apply_PQ(re[q], im[q], c);
        } else {
            constexpr int MC = 1 << (8 - C);
            CoefPQ c0 = mkPQ(m), c1 = mkPQ(m + 8);
#pragma unroll
            for (int q = 0; q < 8; q++) apply_PQ(re[q], im[q], (q & MC) ? c1 : c0);
        }
    } else {
        constexpr int MT = 1 << (8 - T);
        if constexpr (C < 5) {
            const float* mm = (lane & (1 << (4 - C))) ? m + 8 : m;
            CoefM c = mkM(mm);
#pragma unroll
            for (int q = 0; q < 8; q++) if (!(q & MT))
                apply_pair(re[q], im[q], re[q | MT], im[q | MT], c);
        } else if constexpr (C == 5) {
            CoefM c = mkM2(m);
#pragma unroll
            for (int q = 0; q < 8; q++) if (!(q & MT))
                apply_pair(re[q], im[q], re[q | MT], im[q | MT], c);
        } else {
            constexpr int MC = 1 << (8 - C);
            {
                CoefM c = mkM(m);
#pragma unroll
                for (int q = 0; q < 8; q++) if (!(q & MT) && !(q & MC))
                    apply_pair(re[q], im[q], re[q | MT], im[q | MT], c);
            }
            {
                CoefM c = mkM(m + 8);
#pragma unroll
                for (int q = 0; q < 8; q++) if (!(q & MT) && (q & MC))
                    apply_pair(re[q], im[q], re[q | MT], im[q | MT], c);
            }
        }
    }
}

// Standalone 1q complex 2x2 on a lane wire (W in {1,2}); o[8]
template<int W>
__device__ __forceinline__ void g_1q(u64 (&re)[8], u64 (&im)[8], const float* o, int lane) {
    constexpr int LMT = 1 << (4 - W);
    bool tbit = (lane & LMT) != 0;
    SEL_AB(o, tbit, Ar, Ai, Br, Bi);
    CoefAB c = mkAB(Ar, Ai, Br, Bi);
#pragma unroll
    for (int q = 0; q < 8; q++) {
        u64 pre = shx(re[q], LMT), pim = shx(im[q], LMT);
        apply_AB(re[q], im[q], pre, pim, c);
    }
}

// ------------------------- prep: complex 2x2 algebra -----------------------
struct cpx { float r, i; };
__device__ __forceinline__ cpx cmulh(cpx x, cpx y) {
    return { x.r * y.r - x.i * y.i, x.r * y.i + x.i * y.r };
}
__device__ __forceinline__ cpx caddh(cpx x, cpx y) { return { x.r + y.r, x.i + y.i }; }
struct mat2 { cpx m00, m01, m10, m11; };
__device__ mat2 mmul(mat2 A, mat2 B) {
    return { caddh(cmulh(A.m00, B.m00), cmulh(A.m01, B.m10)),
             caddh(cmulh(A.m00, B.m01), cmulh(A.m01, B.m11)),
             caddh(cmulh(A.m10, B.m00), cmulh(A.m11, B.m10)),
             caddh(cmulh(A.m10, B.m01), cmulh(A.m11, B.m11)) };
}
__device__ mat2 mI() { return { {1,0},{0,0},{0,0},{1,0} }; }
__device__ mat2 mX() { return { {0,0},{1,0},{1,0},{0,0} }; }
__device__ mat2 mRY(float t) {
    float c, s; sincosf(0.5f * t, &s, &c);
    return { {c,0},{-s,0},{s,0},{c,0} };
}
__device__ mat2 mRot(const float* w) {
    float phi = w[0], th = w[1], om = w[2];
    float ct, st; sincosf(0.5f * th, &st, &ct);
    float ca, sa; sincosf(0.5f * (phi + om), &sa, &ca);
    float cb, sb; sincosf(0.5f * (phi - om), &sb, &cb);
    return { { ct * ca, -ct * sa }, { -st * cb, -st * sb },
             { st * cb, -st * sb }, { ct * ca,  ct * sa } };
}
__device__ mat2 mK0(float pb) {
    float cb, sb; sincosf(0.5f * pb, &sb, &cb);
    return { {sb,0},{cb,0},{cb,0},{-sb,0} };
}
__device__ mat2 mK1(float pb, float pz, float px) {
    float cb, sb; sincosf(0.5f * pb, &sb, &cb);
    float cz, sz; sincosf(0.5f * pz, &sz, &cz);
    float cx, sx; sincosf(0.5f * px, &sx, &cx);
    float d00r =  cz * cb, d00i =  sz * cb;
    float d01r = -cz * sb, d01i = -sz * sb;
    float d10r =  cz * sb, d10i = -sz * sb;
    float d11r =  cz * cb, d11i = -sz * cb;
    mat2 W;
    W.m00 = {  cx * d00r + sx * d10i,  cx * d00i - sx * d10r };
    W.m01 = {  cx * d01r + sx * d11i,  cx * d01i - sx * d11r };
    W.m10 = {  sx * d00i + cx * d10r, -sx * d00r + cx * d10i };
    W.m11 = {  sx * d01i + cx * d11r, -sx * d01r + cx * d11i };
    return W;
}
__device__ __forceinline__ void store8(float* o, mat2 M) {
    o[0] = M.m00.r; o[1] = M.m00.i; o[2] = M.m01.r; o[3] = M.m01.i;
    o[4] = M.m10.r; o[5] = M.m10.i; o[6] = M.m11.r; o[7] = M.m11.i;
}

// in-block prep: identical fusion logic as the R6 prep kernel, into shared
__device__ void prep_shared(float* sh, const float* params,
                            const float* weights, const float* params2, int t) {
    if ((t < 27) || (t >= 54 && t < 99)) {
        int b = (t < 27) ? t / 9 : 3 + (t - 54) / 9;
        int i = (t < 27) ? t % 9 : (t - 54) % 9;
        const float* pb_ = (b < 3) ? params + b * 36 : params2 + (b - 3) * 36;
        float bb = pb_[i * 4 + 1], zz = pb_[i * 4 + 2], xx = pb_[i * 4 + 3];
        mat2 M0 = mK0(bb), M1 = mK1(bb, zz, xx);
        mat2 U;
        if (i < 8) {
            U = mRY(pb_[(i + 1) * 4 + 0]);
        } else if (b == 2) {
            U = mRot(weights + 0);
        } else if (b == 7) {
            U = mI();
        } else {
            const float* nb = (b + 1 < 3) ? params + (b + 1) * 36
                                          : params2 + (b + 1 - 3) * 36;
            U = mRY(nb[0]);
        }
        M0 = mmul(U, M0); M1 = mmul(U, M1);
        float* o = sh + t * 16;
        store8(o, M0); store8(o + 8, M1);
    } else if (t >= 27 && t < 54) {
        int L = (t - 27) / 9, i = (t - 27) % 9, r = L + 1;
        int tt = (i + r) % 9;
        mat2 R = mI(), Lt = mI();
        if (L == 0 && i < 8) R = mRot(weights + (0 * 9 + tt) * 3);
        if (L == 1 && i < 7) R = mRot(weights + (1 * 9 + tt) * 3);
        if (L == 2 && i < 6) R = mRot(weights + (2 * 9 + tt) * 3);
        if (L == 0 && i == 8) Lt = mRot(weights + (1 * 9 + 0) * 3);
        if (L == 1 && i == 7) Lt = mRot(weights + (2 * 9 + 0) * 3);
        if (L == 1 && i == 8) Lt = mRot(weights + (2 * 9 + 1) * 3);
        if (L == 2 && i == 6) Lt = mRY(params2[0]);
        mat2 M0 = mmul(Lt, R);
        mat2 M1 = mmul(Lt, mmul(mX(), R));
        float* o = sh + t * 16;
        store8(o, M0); store8(o + 8, M1);
    } else if (t == 99) {
        store8(sh + R1OFF, mRot(weights + (1 * 9 + 1) * 3));
    } else if (t == 100) {
        store8(sh + R2OFF, mRot(weights + (2 * 9 + 2) * 3));
    } else if (t == 101) {
        float c, s; sincosf(0.5f * params[0], &s, &c);
        sh[RY0OFF] = c; sh[RY0OFF + 1] = s;
    }
}

// ------------------------------- sim kernel --------------------------------
__global__ void __launch_bounds__(128, 6)
sim_kernel(const float* __restrict__ adds,
           const float* __restrict__ params,
           const float* __restrict__ weights,
           const float* __restrict__ params2,
           float* __restrict__ out, int B) {
    __shared__ float sh[N_COEF];
    prep_shared(sh, params, weights, params2, threadIdx.x);
    __syncthreads();

    int lane = threadIdx.x & 31;
    int item = blockIdx.x * (blockDim.x >> 5) + (threadIdx.x >> 5);
    if (item >= B) return;

    // per-sample embedding angles
    float ec = 1.f, es = 0.f;
    if (lane < 9) {
        float a = adds[item * 9 + lane];
        sincosf(0.5f * a, &es, &ec);
    }
    float cw[9], sw[9];
#pragma unroll
    for (int w = 0; w < 9; w++) {
        cw[w] = __shfl_sync(0xffffffffu, ec, w);
        sw[w] = __shfl_sync(0xffffffffu, es, w);
    }

    // Tensor-product init (RY_0^{(0)} fused into wire-0 factor)
    float magl = ((lane & 8) ? sw[1] : cw[1]) * ((lane & 4) ? sw[2] : cw[2])
               * ((lane & 2) ? sw[3] : cw[3]) * ((lane & 1) ? sw[4] : cw[4]);
    int klane = __popc(lane & 15);
    bool b0 = (lane & 16) != 0;
    float ca0 = sh[RY0OFF], sa0 = sh[RY0OFF + 1];
    float v0r = b0 ? sa0 * cw[0] : ca0 * cw[0];
    float v0i = b0 ? -ca0 * sw[0] : sa0 * sw[0];

    float reA[16], imA[16];
    static_for<16>([&](auto rc) {
        constexpr int R = decltype(rc)::value;
        float mr = ((R & 8) ? sw[5] : cw[5]) * ((R & 4) ? sw[6] : cw[6])
                 * ((R & 2) ? sw[7] : cw[7]) * ((R & 1) ? sw[8] : cw[8]);
        float v = magl * mr;
        constexpr int KR = ((R >> 3) & 1) + ((R >> 2) & 1) + ((R >> 1) & 1) + (R & 1);
        int k = (klane + KR) & 3;
        reA[R] = (k == 0) ?  v * v0r : (k == 1) ?  v * v0i
               : (k == 2) ? -v * v0r :            -v * v0i;
        imA[R] = (k == 0) ?  v * v0i : (k == 1) ? -v * v0r
               : (k == 2) ? -v * v0i :             v * v0r;
    });
    u64 re[8], im[8];
    static_for<8>([&](auto qc) {
        constexpr int Q = decltype(qc)::value;
        re[Q] = pk2(reA[Q], reA[Q + 8]);
        im[Q] = pk2(imA[Q], imA[Q + 8]);
    });

    // QRAM blocks 0..2
    static_for<3>([&](auto bc) {
        constexpr int Bb = decltype(bc)::value;
        static_for<9>([&](auto ic) {
            constexpr int I = decltype(ic)::value;
            gate<I, (I + 1) % 9>(re, im, sh + (Bb * 9 + I) * 16, lane);
        });
    });

    // SEL L0
    static_for<9>([&](auto ic) {
        constexpr int I = decltype(ic)::value;
        gate<I, (I + 1) % 9>(re, im, sh + (27 + I) * 16, lane);
    });
    g_1q<1>(re, im, sh + R1OFF, lane);
    // SEL L1
    static_for<9>([&](auto ic) {
        constexpr int I = decltype(ic)::value;
        gate<I, (I + 2) % 9>(re, im, sh + (36 + I) * 16, lane);
    });
    g_1q<2>(re, im, sh + R2OFF, lane);
    // SEL L2
    static_for<9>([&](auto ic) {
        constexpr int I = decltype(ic)::value;
        gate<I, (I + 3) % 9>(re, im, sh + (45 + I) * 16, lane);
    });

    // classifier blocks 3..7
    static_for<5>([&](auto bc) {
        constexpr int Bb = decltype(bc)::value;
        static_for<9>([&](auto ic) {
            constexpr int I = decltype(ic)::value;
            gate<I, (I + 1) % 9>(re, im, sh + (54 + Bb * 9 + I) * 16, lane);
        });
    });

    // <Z0>: wire 0 = lane bit 4
    u64 acc2 = 0ull;
#pragma unroll
    for (int q = 0; q < 8; q++)
        acc2 = ffma2(re[q], re[q], ffma2(im[q], im[q], acc2));
    float lo, hi; upk2(acc2, lo, hi);
    float acc = lo + hi;
    if (lane & 16) acc = -acc;
#pragma unroll
    for (int m = 16; m >= 1; m >>= 1) acc += __shfl_xor_sync(0xffffffffu, acc, m);
    if (lane == 0) out[item] = acc;
}

// ------------------------------ launcher -----------------------------------
extern "C" void kernel_launch(void* const* d_in, const int* in_sizes, int n_in,
                              void* d_out, int out_size) {
    const float* adds    = (const float*)d_in[0];
    const float* params  = (const float*)d_in[1];
    const float* weights = (const float*)d_in[2];
    const float* params2 = (const float*)d_in[3];
    float* out = (float*)d_out;

    int B = in_sizes[0] / 9;

    int warpsPerBlock = 4;
    int blocks = (B + warpsPerBlock - 1) / warpsPerBlock;
    sim_kernel<<<blocks, 128>>>(adds, params, weights, params2, out, B);
}

// round 12
// speedup vs baseline: 2.3113x; 1.1195x over previous
#include <cuda_runtime.h>
#include <cuda_bf16.h>

// ---------------------------------------------------------------------------
// 9-wire statevector simulator. One warp per batch item, 16 complex amps/lane.
// SoA f32x2 packing: u64 re[8]/im[8] hold (component of amp q, amp q+8),
// pairing along reg bit 3 (= wire 5).
//
// R10/R11: per-block prep expands every gate's coefficients into shared
// memory, per lane-combo, with broadcast-duplication and negation prebaked,
// so each gate body is pure LDS + f32x2 FMA + SHFL (no SEL/MOV coefficient
// setup). (Re-submission: previous round died on a broker infra failure.)
//
// Amplitude index idx[8:0]: wire w <-> bit (8-w).
//   wires 0..4 -> lane bits 4..0 (shuffles)
//   wire  5    -> f32x2 packed half
//   wires 6..8 -> reg bits 2..0 of q
// ---------------------------------------------------------------------------

using u64 = unsigned long long;

#define N_SLOTS   101                  // 99 fused gates + 2 standalone Rots
#define SLOT_U64  24                   // 192 bytes per gate slot
#define RY0_F     (N_SLOTS * SLOT_U64 * 2)   // float index of (ca,sa)

template<int V> struct IC { static constexpr int value = V; };
template<int N, typename F>
__device__ __forceinline__ void static_for(F&& f) {
    if constexpr (N > 0) { static_for<N - 1>(f); f(IC<N - 1>{}); }
}

// ------------------------- packed f32x2 helpers ----------------------------
__device__ __forceinline__ u64 pk2(float lo, float hi) {
    u64 r;
    asm("mov.b64 %0, {%1, %2};" : "=l"(r)
        : "r"(__float_as_uint(lo)), "r"(__float_as_uint(hi)));
    return r;
}
__device__ __forceinline__ void upk2(u64 a, float& lo, float& hi) {
    unsigned l_, h_;
    asm("mov.b64 {%0, %1}, %2;" : "=r"(l_), "=r"(h_) : "l"(a));
    lo = __uint_as_float(l_); hi = __uint_as_float(h_);
}
__device__ __forceinline__ u64 swp(u64 a) {
    float x, y; upk2(a, x, y); return pk2(y, x);
}
__device__ __forceinline__ u64 ffma2(u64 a, u64 b, u64 c) {
    u64 d; asm("fma.rn.f32x2 %0, %1, %2, %3;" : "=l"(d) : "l"(a), "l"(b), "l"(c));
    return d;
}
__device__ __forceinline__ u64 fmul2(u64 a, u64 b) {
    u64 d; asm("mul.rn.f32x2 %0, %1, %2;" : "=l"(d) : "l"(a), "l"(b));
    return d;
}
__device__ __forceinline__ u64 shx(u64 v, int m) { return __shfl_xor_sync(0xffffffffu, v, m); }

// --------------------- coefficient bundles (loaded from smem) --------------
// AB record (6 u64): Ar,Ai,nAi,Br,Bi,nBi  — out = A*self + B*partner
struct CoefAB { u64 Ar, Ai, nAi, Br, Bi, nBi; };
__device__ __forceinline__ CoefAB ldAB(const u64* r) {
    return { r[0], r[1], r[2], r[3], r[4], r[5] };
}
__device__ __forceinline__ void apply_AB(u64& re, u64& im, u64 pre, u64 pim, const CoefAB& c) {
    u64 nre = ffma2(c.Br, pre, ffma2(c.nBi, pim, ffma2(c.nAi, im, fmul2(c.Ar, re))));
    u64 nim = ffma2(c.Bi, pre, ffma2(c.Br, pim, ffma2(c.Ai, re, fmul2(c.Ar, im))));
    re = nre; im = nim;
}
// PQ (target = packed wire 5): same six-slot record; Ar<->Pr(diag) Br<->Qr(cross)
__device__ __forceinline__ void apply_PQ(u64& re, u64& im, const CoefAB& c) {
    u64 sre = swp(re), sim = swp(im);
    u64 nre = ffma2(c.Br, sre, ffma2(c.nBi, sim, ffma2(c.nAi, im, fmul2(c.Ar, re))));
    u64 nim = ffma2(c.Bi, sre, ffma2(c.Br, sim, ffma2(c.Ai, re, fmul2(c.Ar, im))));
    re = nre; im = nim;
}
// Full 2x2 record (12 u64)
struct CoefM { u64 r00, i00, n00, r01, i01, n01, r10, i10, n10, r11, i11, n11; };
__device__ __forceinline__ CoefM ldM(const u64* r) {
    return { r[0], r[1], r[2], r[3], r[4], r[5], r[6], r[7], r[8], r[9], r[10], r[11] };
}
__device__ __forceinline__ void apply_pair(u64& req, u64& imq, u64& rep, u64& imp, const CoefM& c) {
    u64 nreq = ffma2(c.r01, rep, ffma2(c.n01, imp, ffma2(c.n00, imq, fmul2(c.r00, req))));
    u64 nimq = ffma2(c.i01, rep, ffma2(c.r01, imp, ffma2(c.i00, req, fmul2(c.r00, imq))));
    u64 nrep = ffma2(c.r11, rep, ffma2(c.n11, imp, ffma2(c.n10, imq, fmul2(c.r10, req))));
    u64 nimp = ffma2(c.i11, rep, ffma2(c.r11, imp, ffma2(c.i10, req, fmul2(c.r10, imq))));
    req = nreq; imq = nimq; rep = nrep; imp = nimp;
}

// ------------------------------ gate ---------------------------------------
// g = slot base (u64 units). Record layouts written by prep (see expansion):
//  T<5,C<5 : 4 AB records, lc = cbit*2 + tbit          -> g + lc*6
//  T<5,C>=6: per tbit [c0 AB | c1 AB]                  -> g + tbit*12 (+6)
//  T==5    : per cbit one PQ record                    -> g + cbit*6
//  T>=6,C<5: per cbit one M record                     -> g + cbit*12
//  T>=6,C=5: one mixed-halves M record                 -> g
//  T>=6,C>=6: [M0 record | M1 record]                  -> g, g+12
template<int C, int T>
__device__ __forceinline__ void gate(u64 (&re)[8], u64 (&im)[8], const u64* g, int lane) {
    if constexpr (T < 5) {
        constexpr int LMT = 1 << (4 - T);
        int tb = (lane >> (4 - T)) & 1;
        if constexpr (C < 5) {
            int cb = (lane >> (4 - C)) & 1;
            CoefAB c = ldAB(g + (cb * 2 + tb) * 6);
#pragma unroll
            for (int q = 0; q < 8; q++) {
                u64 pre = shx(re[q], LMT), pim = shx(im[q], LMT);
                apply_AB(re[q], im[q], pre, pim, c);
            }
        } else {   // C >= 6 (C==5,T<5 never occurs in this circuit)
            constexpr int MC = 1 << (8 - C);
            const u64* r = g + tb * 12;
            CoefAB c0 = ldAB(r), c1 = ldAB(r + 6);
#pragma unroll
            for (int q = 0; q < 8; q++) {
                u64 pre = shx(re[q], LMT), pim = shx(im[q], LMT);
                apply_AB(re[q], im[q], pre, pim, (q & MC) ? c1 : c0);
            }
        }
    } else if constexpr (T == 5) {      // control always a lane wire here
        int cb = (lane >> (4 - C)) & 1;
        CoefAB c = ldAB(g + cb * 6);
#pragma unroll
        for (int q = 0; q < 8; q++) apply_PQ(re[q], im[q], c);
    } else {
        constexpr int MT = 1 << (8 - T);
        if constexpr (C < 5) {
            int cb = (lane >> (4 - C)) & 1;
            CoefM c = ldM(g + cb * 12);
#pragma unroll
            for (int q = 0; q < 8; q++) if (!(q & MT))
                apply_pair(re[q], im[q], re[q | MT], im[q | MT], c);
        } else if constexpr (C == 5) {
            CoefM c = ldM(g);
#pragma unroll
            for (int q = 0; q < 8; q++) if (!(q & MT))
                apply_pair(re[q], im[q], re[q | MT], im[q | MT], c);
        } else {
            constexpr int MC = 1 << (8 - C);
            {
                CoefM c = ldM(g);
#pragma unroll
                for (int q = 0; q < 8; q++) if (!(q & MT) && !(q & MC))
                    apply_pair(re[q], im[q], re[q | MT], im[q | MT], c);
            }
            {
                CoefM c = ldM(g + 12);
#pragma unroll
                for (int q = 0; q < 8; q++) if (!(q & MT) && (q & MC))
                    apply_pair(re[q], im[q], re[q | MT], im[q | MT], c);
            }
        }
    }
}

// Standalone 1q on lane wire W: 2 AB records indexed by tbit
template<int W>
__device__ __forceinline__ void g_1q(u64 (&re)[8], u64 (&im)[8], const u64* g, int lane) {
    constexpr int LMT = 1 << (4 - W);
    int tb = (lane >> (4 - W)) & 1;
    CoefAB c = ldAB(g + tb * 6);
#pragma unroll
    for (int q = 0; q < 8; q++) {
        u64 pre = shx(re[q], LMT), pim = shx(im[q], LMT);
        apply_AB(re[q], im[q], pre, pim, c);
    }
}

// ------------------------- prep: complex 2x2 algebra -----------------------
struct cpx { float r, i; };
__device__ __forceinline__ cpx cmulh(cpx x, cpx y) {
    return { x.r * y.r - x.i * y.i, x.r * y.i + x.i * y.r };
}
__device__ __forceinline__ cpx caddh(cpx x, cpx y) { return { x.r + y.r, x.i + y.i }; }
struct mat2 { cpx m00, m01, m10, m11; };
__device__ mat2 mmul(mat2 A, mat2 B) {
    return { caddh(cmulh(A.m00, B.m00), cmulh(A.m01, B.m10)),
             caddh(cmulh(A.m00, B.m01), cmulh(A.m01, B.m11)),
             caddh(cmulh(A.m10, B.m00), cmulh(A.m11, B.m10)),
             caddh(cmulh(A.m10, B.m01), cmulh(A.m11, B.m11)) };
}
__device__ mat2 mI() { return { {1,0},{0,0},{0,0},{1,0} }; }
__device__ mat2 mX() { return { {0,0},{1,0},{1,0},{0,0} }; }
__device__ mat2 mRY(float t) {
    float c, s; sincosf(0.5f * t, &s, &c);
    return { {c,0},{-s,0},{s,0},{c,0} };
}
__device__ mat2 mRot(const float* w) {
    float phi = w[0], th = w[1], om = w[2];
    float ct, st; sincosf(0.5f * th, &st, &ct);
    float ca, sa; sincosf(0.5f * (phi + om), &sa, &ca);
    float cb, sb; sincosf(0.5f * (phi - om), &sb, &cb);
    return { { ct * ca, -ct * sa }, { -st * cb, -st * sb },
             { st * cb, -st * sb }, { ct * ca,  ct * sa } };
}
__device__ mat2 mK0(float pb) {
    float cb, sb; sincosf(0.5f * pb, &sb, &cb);
    return { {sb,0},{cb,0},{cb,0},{-sb,0} };
}
__device__ mat2 mK1(float pb, float pz, float px) {
    float cb, sb; sincosf(0.5f * pb, &sb, &cb);
    float cz, sz; sincosf(0.5f * pz, &sz, &cz);
    float cx, sx; sincosf(0.5f * px, &sx, &cx);
    float d00r =  cz * cb, d00i =  sz * cb;
    float d01r = -cz * sb, d01i = -sz * sb;
    float d10r =  cz * sb, d10i = -sz * sb;
    float d11r =  cz * cb, d11i = -sz * cb;
    mat2 W;
    W.m00 = {  cx * d00r + sx * d10i,  cx * d00i - sx * d10r };
    W.m01 = {  cx * d01r + sx * d11i,  cx * d01i - sx * d11r };
    W.m10 = {  sx * d00i + cx * d10r, -sx * d00r + cx * d10i };
    W.m11 = {  sx * d01i + cx * d11r, -sx * d01r + cx * d11i };
    return W;
}

// ---- record writers (float offsets) ----
__device__ __forceinline__ cpx selA(const mat2& M, int tb) { return tb ? M.m11 : M.m00; }
__device__ __forceinline__ cpx selB(const mat2& M, int tb) { return tb ? M.m10 : M.m01; }
__device__ void wAB(float* o, cpx A, cpx B) {
    o[0] = A.r; o[1] = A.r; o[2] = A.i; o[3] = A.i; o[4] = -A.i; o[5] = -A.i;
    o[6] = B.r; o[7] = B.r; o[8] = B.i; o[9] = B.i; o[10] = -B.i; o[11] = -B.i;
}
__device__ void wM(float* o, mat2 M) {
    cpx v[4] = { M.m00, M.m01, M.m10, M.m11 };
    for (int k = 0; k < 4; k++) {
        o[k*6+0] = v[k].r; o[k*6+1] = v[k].r;
        o[k*6+2] = v[k].i; o[k*6+3] = v[k].i;
        o[k*6+4] = -v[k].i; o[k*6+5] = -v[k].i;
    }
}
__device__ void wMmix(float* o, mat2 A, mat2 B) {   // halves (A=ctrl0, B=ctrl1) on wire5
    cpx va[4] = { A.m00, A.m01, A.m10, A.m11 };
    cpx vb[4] = { B.m00, B.m01, B.m10, B.m11 };
    for (int k = 0; k < 4; k++) {
        o[k*6+0] = va[k].r; o[k*6+1] = vb[k].r;
        o[k*6+2] = va[k].i; o[k*6+3] = vb[k].i;
        o[k*6+4] = -va[k].i; o[k*6+5] = -vb[k].i;
    }
}
__device__ void wPQ(float* o, mat2 M) {   // P=(m00,m11) diag halves, Q=(m01,m10)
    o[0] = M.m00.r; o[1] = M.m11.r; o[2] = M.m00.i; o[3] = M.m11.i;
    o[4] = -M.m00.i; o[5] = -M.m11.i;
    o[6] = M.m01.r; o[7] = M.m10.r; o[8] = M.m01.i; o[9] = M.m10.i;
    o[10] = -M.m01.i; o[11] = -M.m10.i;
}

// expand gate (C,T) with blocks M0,M1 into slot table
__device__ void expand(float* o, int C, int T, mat2 M0, mat2 M1) {
    if (T < 5 && C < 5) {
        for (int cb = 0; cb < 2; cb++) for (int tb = 0; tb < 2; tb++) {
            mat2& M = cb ? M1 : M0;
            wAB(o + (cb * 2 + tb) * 12, selA(M, tb), selB(M, tb));
        }
    } else if (T < 5) {                    // C >= 6
        for (int tb = 0; tb < 2; tb++) {
            wAB(o + tb * 24,      selA(M0, tb), selB(M0, tb));
            wAB(o + tb * 24 + 12, selA(M1, tb), selB(M1, tb));
        }
    } else if (T == 5) {                   // C < 5 always
        wPQ(o, M0); wPQ(o + 12, M1);
    } else if (C == 5) {
        wMmix(o, M0, M1);
    } else {                               // C<5 or C>=6: [M0 | M1] records
        wM(o, M0); wM(o + 24, M1);
    }
}

// in-block prep: fusion logic identical to R9, then per-lane expansion
__device__ void prep_shared(float* fs, const float* params,
                            const float* weights, const float* params2, int t) {
    if ((t < 27) || (t >= 54 && t < 99)) {
        int b = (t < 27) ? t / 9 : 3 + (t - 54) / 9;
        int i = (t < 27) ? t % 9 : (t - 54) % 9;
        const float* pb_ = (b < 3) ? params + b * 36 : params2 + (b - 3) * 36;
        float bb = pb_[i * 4 + 1], zz = pb_[i * 4 + 2], xx = pb_[i * 4 + 3];
        mat2 M0 = mK0(bb), M1 = mK1(bb, zz, xx);
        mat2 U;
        if (i < 8) {
            U = mRY(pb_[(i + 1) * 4 + 0]);
        } else if (b == 2) {
            U = mRot(weights + 0);
        } else if (b == 7) {
            U = mI();
        } else {
            const float* nb = (b + 1 < 3) ? params + (b + 1) * 36
                                          : params2 + (b + 1 - 3) * 36;
            U = mRY(nb[0]);
        }
        M0 = mmul(U, M0); M1 = mmul(U, M1);
        expand(fs + t * 48, i, (i + 1) % 9, M0, M1);
    } else if (t >= 27 && t < 54) {
        int L = (t - 27) / 9, i = (t - 27) % 9, r = L + 1;
        int tt = (i + r) % 9;
        mat2 R = mI(), Lt = mI();
        if (L == 0 && i < 8) R = mRot(weights + (0 * 9 + tt) * 3);
        if (L == 1 && i < 7) R = mRot(weights + (1 * 9 + tt) * 3);
        if (L == 2 && i < 6) R = mRot(weights + (2 * 9 + tt) * 3);
        if (L == 0 && i == 8) Lt = mRot(weights + (1 * 9 + 0) * 3);
        if (L == 1 && i == 7) Lt = mRot(weights + (2 * 9 + 0) * 3);
        if (L == 1 && i == 8) Lt = mRot(weights + (2 * 9 + 1) * 3);
        if (L == 2 && i == 6) Lt = mRY(params2[0]);
        mat2 M0 = mmul(Lt, R);
        mat2 M1 = mmul(Lt, mmul(mX(), R));
        expand(fs + t * 48, i, tt, M0, M1);
    } else if (t == 99) {                  // Rot(L1, wire1): 2 AB records by tbit
        mat2 M = mRot(weights + (1 * 9 + 1) * 3);
        float* o = fs + 99 * 48;
        wAB(o, selA(M, 0), selB(M, 0));
        wAB(o + 12, selA(M, 1), selB(M, 1));
    } else if (t == 100) {                 // Rot(L2, wire2)
        mat2 M = mRot(weights + (2 * 9 + 2) * 3);
        float* o = fs + 100 * 48;
        wAB(o, selA(M, 0), selB(M, 0));
        wAB(o + 12, selA(M, 1), selB(M, 1));
    } else if (t == 101) {
        float c, s; sincosf(0.5f * params[0], &s, &c);
        fs[RY0_F] = c; fs[RY0_F + 1] = s;
    }
}

// ------------------------------- sim kernel --------------------------------
__global__ void __launch_bounds__(128, 7)
sim_kernel(const float* __restrict__ adds,
           const float* __restrict__ params,
           const float* __restrict__ weights,
           const float* __restrict__ params2,
           float* __restrict__ out, int B) {
    __shared__ __align__(16) u64 shu[N_SLOTS * SLOT_U64 + 1];
    prep_shared((float*)shu, params, weights, params2, threadIdx.x);
    __syncthreads();
    const float* fs = (const float*)shu;

    int lane = threadIdx.x & 31;
    int item = blockIdx.x * (blockDim.x >> 5) + (threadIdx.x >> 5);
    if (item >= B) return;

    // per-sample embedding angles
    float ec = 1.f, es = 0.f;
    if (lane < 9) {
        float a = adds[item * 9 + lane];
        sincosf(0.5f * a, &es, &ec);
    }
    float cw[9], sw[9];
#pragma unroll
    for (int w = 0; w < 9; w++) {
        cw[w] = __shfl_sync(0xffffffffu, ec, w);
        sw[w] = __shfl_sync(0xffffffffu, es, w);
    }

    // Tensor-product init (RY_0^{(0)} fused into wire-0 factor)
    float magl = ((lane & 8) ? sw[1] : cw[1]) * ((lane & 4) ? sw[2] : cw[2])
               * ((lane & 2) ? sw[3] : cw[3]) * ((lane & 1) ? sw[4] : cw[4]);
    int klane = __popc(lane & 15);
    bool b0 = (lane & 16) != 0;
    float ca0 = fs[RY0_F], sa0 = fs[RY0_F + 1];
    float v0r = b0 ? sa0 * cw[0] : ca0 * cw[0];
    float v0i = b0 ? -ca0 * sw[0] : sa0 * sw[0];

    float reA[16], imA[16];
    static_for<16>([&](auto rc) {
        constexpr int R = decltype(rc)::value;
        float mr = ((R & 8) ? sw[5] : cw[5]) * ((R & 4) ? sw[6] : cw[6])
                 * ((R & 2) ? sw[7] : cw[7]) * ((R & 1) ? sw[8] : cw[8]);
        float v = magl * mr;
        constexpr int KR = ((R >> 3) & 1) + ((R >> 2) & 1) + ((R >> 1) & 1) + (R & 1);
        int k = (klane + KR) & 3;
        reA[R] = (k == 0) ?  v * v0r : (k == 1) ?  v * v0i
               : (k == 2) ? -v * v0r :            -v * v0i;
        imA[R] = (k == 0) ?  v * v0i : (k == 1) ? -v * v0r
               : (k == 2) ? -v * v0i :             v * v0r;
    });
    u64 re[8], im[8];
    static_for<8>([&](auto qc) {
        constexpr int Q = decltype(qc)::value;
        re[Q] = pk2(reA[Q], reA[Q + 8]);
        im[Q] = pk2(imA[Q], imA[Q + 8]);
    });

#define SLOT(s) (shu + (s) * SLOT_U64)

    // QRAM blocks 0..2
    static_for<3>([&](auto bc) {
        constexpr int Bb = decltype(bc)::value;
        static_for<9>([&](auto ic) {
            constexpr int I = decltype(ic)::value;
            gate<I, (I + 1) % 9>(re, im, SLOT(Bb * 9 + I), lane);
        });
    });

    // SEL L0
    static_for<9>([&](auto ic) {
        constexpr int I = decltype(ic)::value;
        gate<I, (I + 1) % 9>(re, im, SLOT(27 + I), lane);
    });
    g_1q<1>(re, im, SLOT(99), lane);
    // SEL L1
    static_for<9>([&](auto ic) {
        constexpr int I = decltype(ic)::value;
        gate<I, (I + 2) % 9>(re, im, SLOT(36 + I), lane);
    });
    g_1q<2>(re, im, SLOT(100), lane);
    // SEL L2
    static_for<9>([&](auto ic) {
        constexpr int I = decltype(ic)::value;
        gate<I, (I + 3) % 9>(re, im, SLOT(45 + I), lane);
    });

    // classifier blocks 3..7
    static_for<5>([&](auto bc) {
        constexpr int Bb = decltype(bc)::value;
        static_for<9>([&](auto ic) {
            constexpr int I = decltype(ic)::value;
            gate<I, (I + 1) % 9>(re, im, SLOT(54 + Bb * 9 + I), lane);
        });
    });

    // <Z0>: wire 0 = lane bit 4
    u64 acc2 = 0ull;
#pragma unroll
    for (int q = 0; q < 8; q++)
        acc2 = ffma2(re[q], re[q], ffma2(im[q], im[q], acc2));
    float lo, hi; upk2(acc2, lo, hi);
    float acc = lo + hi;
    if (lane & 16) acc = -acc;
#pragma unroll
    for (int m = 16; m >= 1; m >>= 1) acc += __shfl_xor_sync(0xffffffffu, acc, m);
    if (lane == 0) out[item] = acc;
}

// ------------------------------ launcher -----------------------------------
extern "C" void kernel_launch(void* const* d_in, const int* in_sizes, int n_in,
                              void* d_out, int out_size) {
    const float* adds    = (const float*)d_in[0];
    const float* params  = (const float*)d_in[1];
    const float* weights = (const float*)d_in[2];
    const float* params2 = (const float*)d_in[3];
    float* out = (float*)d_out;

    int B = in_sizes[0] / 9;

    int warpsPerBlock = 4;
    int blocks = (B + warpsPerBlock - 1) / warpsPerBlock;
    sim_kernel<<<blocks, 128>>>(adds, params, weights, params2, out, B);
}